// round 2
// baseline (speedup 1.0000x reference)
#include <cuda_runtime.h>
#include <math.h>

#define N_NODES  50000
#define N_EDGES  800000
#define E_TOT    (N_EDGES + N_NODES)   // self-loops appended
#define N_GRAPHS 256
#define FEAT     128
#define HID      64
#define HEADS    4
#define HH       (HID*HEADS)           // 256
#define OUTF     128
#define NEG_SLOPE 0.2f

// ---------------- scratch (device globals; no allocs allowed) ----------------
__device__ float g_h[(size_t)N_NODES*HH];     // GEMM output (per-layer features)
__device__ float g_x[(size_t)N_NODES*HH];     // aggregation output -> next layer input
__device__ float g_as[N_NODES*HEADS];
__device__ float g_ad[N_NODES*HEADS];
__device__ float g_m[N_NODES*HEADS];
__device__ float g_s[N_NODES*HEADS];
__device__ float g_e[(size_t)E_TOT*HEADS];
__device__ float g_pool[N_GRAPHS*HH];
__device__ float g_cnt[N_GRAPHS];

// ---------------- helpers ----------------
__device__ __forceinline__ void atomicMaxF(float* addr, float val) {
    int* ai = (int*)addr;
    int old = *ai;
    while (__int_as_float(old) < val) {
        int prev = atomicCAS(ai, old, __float_as_int(val));
        if (prev == old) break;
        old = prev;
    }
}

__device__ __forceinline__ void edge_src_dst(int e, const int* ei, int& src, int& dst) {
    if (e < N_EDGES) {
        src = ei[e];
        dst = ei[N_EDGES + e];
    } else {
        src = dst = e - N_EDGES;   // self-loop
    }
}

// ---------------- GEMM: C[N,256] = A[N,K] @ B[K,256] ----------------
// 64x64 block tile, 256 threads, 4x4 per-thread micro-tile, K-step 16.
// If A == nullptr, read from g_x (device-global ping-pong buffer).
__global__ void gemm64(const float* __restrict__ A_in, const float* __restrict__ B,
                       int N, int K) {
    const int M = HH;
    const float* A = A_in ? A_in : g_x;
    __shared__ float As[16][64];
    __shared__ float Bs[16][68];

    int tid = threadIdx.x;
    int tx = tid & 15, ty = tid >> 4;
    int rowBase = blockIdx.y * 64;
    int colBase = blockIdx.x * 64;

    float acc[4][4] = {};

    for (int k0 = 0; k0 < K; k0 += 16) {
        #pragma unroll
        for (int i = 0; i < 4; i++) {
            int idx = tid + i * 256;       // 0..1023
            int r  = idx >> 4;
            int kk = idx & 15;
            int gr = rowBase + r;
            As[kk][r] = (gr < N) ? A[(size_t)gr * K + k0 + kk] : 0.f;
        }
        #pragma unroll
        for (int i = 0; i < 4; i++) {
            int idx = tid + i * 256;
            int kk = idx >> 6;
            int c  = idx & 63;
            Bs[kk][c] = B[(size_t)(k0 + kk) * M + colBase + c];
        }
        __syncthreads();
        #pragma unroll
        for (int kk = 0; kk < 16; kk++) {
            float a[4], b[4];
            #pragma unroll
            for (int i = 0; i < 4; i++) a[i] = As[kk][ty * 4 + i];
            #pragma unroll
            for (int j = 0; j < 4; j++) b[j] = Bs[kk][tx * 4 + j];
            #pragma unroll
            for (int i = 0; i < 4; i++)
                #pragma unroll
                for (int j = 0; j < 4; j++)
                    acc[i][j] += a[i] * b[j];
        }
        __syncthreads();
    }

    #pragma unroll
    for (int i = 0; i < 4; i++) {
        int r = rowBase + ty * 4 + i;
        if (r < N) {
            #pragma unroll
            for (int j = 0; j < 4; j++)
                g_h[(size_t)r * M + colBase + tx * 4 + j] = acc[i][j];
        }
    }
}

// ---------------- per-(node,head) attention logits ----------------
__global__ void alphas_kernel(const float* __restrict__ a_s, const float* __restrict__ a_d) {
    int task = blockIdx.x * 8 + (threadIdx.x >> 5);
    int lane = threadIdx.x & 31;
    if (task >= N_NODES * HEADS) return;
    int n = task >> 2;
    int h = task & 3;
    const float* hp = g_h + (size_t)n * HH + h * HID;
    float v0 = hp[lane], v1 = hp[lane + 32];
    float s0 = a_s[h * HID + lane], s1 = a_s[h * HID + lane + 32];
    float d0 = a_d[h * HID + lane], d1 = a_d[h * HID + lane + 32];
    float vs = v0 * s0 + v1 * s1;
    float vd = v0 * d0 + v1 * d1;
    #pragma unroll
    for (int off = 16; off > 0; off >>= 1) {
        vs += __shfl_down_sync(0xffffffffu, vs, off);
        vd += __shfl_down_sync(0xffffffffu, vd, off);
    }
    if (lane == 0) {
        g_as[task] = vs;
        g_ad[task] = vd;
    }
}

// ---------------- init m=-inf, s=0, x(agg target)=0 ----------------
__global__ void init_layer_kernel() {
    int idx = blockIdx.x * blockDim.x + threadIdx.x;
    if (idx < N_NODES * HH) g_x[idx] = 0.f;
    if (idx < N_NODES * HEADS) {
        g_m[idx] = -INFINITY;
        g_s[idx] = 0.f;
    }
}

// ---------------- pass A: e = leaky_relu(as[src]+ad[dst]); segment max ----------------
__global__ void edge_max_kernel(const int* __restrict__ ei) {
    int e = blockIdx.x * blockDim.x + threadIdx.x;
    if (e >= E_TOT) return;
    int src, dst;
    edge_src_dst(e, ei, src, dst);
    #pragma unroll
    for (int h = 0; h < HEADS; h++) {
        float v = g_as[src * HEADS + h] + g_ad[dst * HEADS + h];
        v = (v > 0.f) ? v : NEG_SLOPE * v;
        g_e[(size_t)e * HEADS + h] = v;
        atomicMaxF(&g_m[dst * HEADS + h], v);
    }
}

// ---------------- pass B: ex = exp(e - m[dst]); segment sum ----------------
__global__ void edge_exp_kernel(const int* __restrict__ ei) {
    int e = blockIdx.x * blockDim.x + threadIdx.x;
    if (e >= E_TOT) return;
    int src, dst;
    edge_src_dst(e, ei, src, dst);
    (void)src;
    #pragma unroll
    for (int h = 0; h < HEADS; h++) {
        float ex = expf(g_e[(size_t)e * HEADS + h] - g_m[dst * HEADS + h]);
        g_e[(size_t)e * HEADS + h] = ex;
        atomicAdd(&g_s[dst * HEADS + h], ex);
    }
}

// ---------------- pass C: out[dst] += h[src] * alpha ----------------
// warp per edge; lanes cover 256 features coalesced
__global__ void edge_agg_kernel(const int* __restrict__ ei) {
    int e = blockIdx.x * 8 + (threadIdx.x >> 5);
    int lane = threadIdx.x & 31;
    if (e >= E_TOT) return;
    int src, dst;
    edge_src_dst(e, ei, src, dst);

    float a = 0.f;
    if (lane < HEADS)
        a = g_e[(size_t)e * HEADS + lane] / g_s[dst * HEADS + lane];

    const float* hs = g_h + (size_t)src * HH;
    float* od = g_x + (size_t)dst * HH;
    #pragma unroll
    for (int j0 = 0; j0 < HH; j0 += 32) {
        int j = j0 + lane;
        float al = __shfl_sync(0xffffffffu, a, j >> 6);
        atomicAdd(&od[j], hs[j] * al);
    }
}

// ---------------- bias + ELU (in place on g_x) ----------------
__global__ void bias_elu_kernel(const float* __restrict__ b) {
    int idx = blockIdx.x * blockDim.x + threadIdx.x;
    if (idx >= N_NODES * HH) return;
    float v = g_x[idx] + b[idx & (HH - 1)];
    g_x[idx] = (v > 0.f) ? v : expm1f(v);
}

// ---------------- pooling ----------------
__global__ void pool_zero_kernel() {
    int idx = blockIdx.x * blockDim.x + threadIdx.x;
    if (idx < N_GRAPHS * HH) g_pool[idx] = 0.f;
    if (idx < N_GRAPHS) g_cnt[idx] = 0.f;
}

__global__ void pool_kernel(const int* __restrict__ batch) {
    int idx = blockIdx.x * blockDim.x + threadIdx.x;
    if (idx >= N_NODES * HH) return;
    int n = idx >> 8;           // /256
    int f = idx & (HH - 1);
    int g = batch[n];
    atomicAdd(&g_pool[g * HH + f], g_x[idx]);
    if (f == 0) atomicAdd(&g_cnt[g], 1.0f);
}

// ---------------- final: y = (pool/cnt) @ Wf + bf; L2-normalize rows ----------------
__global__ void final_kernel(const float* __restrict__ Wf, const float* __restrict__ bf,
                             float* __restrict__ out) {
    __shared__ float gs[HH];
    __shared__ float red[OUTF];
    int g = blockIdx.x;
    int t = threadIdx.x;        // 0..127
    float cnt = fmaxf(g_cnt[g], 1.0f);
    for (int i = t; i < HH; i += OUTF) gs[i] = g_pool[g * HH + i] / cnt;
    __syncthreads();
    float acc = bf[t];
    #pragma unroll 8
    for (int k = 0; k < HH; k++)
        acc += gs[k] * Wf[(size_t)k * OUTF + t];
    red[t] = acc * acc;
    __syncthreads();
    #pragma unroll
    for (int off = 64; off > 0; off >>= 1) {
        if (t < off) red[t] += red[t + off];
        __syncthreads();
    }
    float norm = fmaxf(sqrtf(red[0]), 1e-12f);
    out[(size_t)g * OUTF + t] = acc / norm;
}

// ---------------- host orchestration ----------------
extern "C" void kernel_launch(void* const* d_in, const int* in_sizes, int n_in,
                              void* d_out, int out_size) {
    const float* x     = (const float*)d_in[0];
    const int*   ei    = (const int*)d_in[1];     // int32: JAX x64 disabled
    const int*   batch = (const int*)d_in[2];
    const float* W[3]  = {(const float*)d_in[3],  (const float*)d_in[7],  (const float*)d_in[11]};
    const float* AS[3] = {(const float*)d_in[4],  (const float*)d_in[8],  (const float*)d_in[12]};
    const float* AD[3] = {(const float*)d_in[5],  (const float*)d_in[9],  (const float*)d_in[13]};
    const float* Bb[3] = {(const float*)d_in[6],  (const float*)d_in[10], (const float*)d_in[14]};
    const float* Wf = (const float*)d_in[15];
    const float* bf = (const float*)d_in[16];
    float* out = (float*)d_out;

    const int threads = 256;
    const int edge_blocks      = (E_TOT + threads - 1) / threads;
    const int edge_warp_blocks = (E_TOT + 7) / 8;
    const int node_feat_blocks = (N_NODES * HH + threads - 1) / threads;
    const int alpha_blocks     = (N_NODES * HEADS + 7) / 8;

    int Din = FEAT;
    const float* in_ptr = x;    // layer 0 reads harness input; later layers read g_x

    for (int l = 0; l < 3; l++) {
        dim3 gg(HH / 64, (N_NODES + 63) / 64);
        gemm64<<<gg, 256>>>(in_ptr, W[l], N_NODES, Din);
        alphas_kernel<<<alpha_blocks, 256>>>(AS[l], AD[l]);
        init_layer_kernel<<<node_feat_blocks, threads>>>();
        edge_max_kernel<<<edge_blocks, threads>>>(ei);
        edge_exp_kernel<<<edge_blocks, threads>>>(ei);
        edge_agg_kernel<<<edge_warp_blocks, 256>>>(ei);
        bias_elu_kernel<<<node_feat_blocks, threads>>>(Bb[l]);
        in_ptr = nullptr;
        Din = HH;
    }

    pool_zero_kernel<<<(N_GRAPHS * HH + threads - 1) / threads, threads>>>();
    pool_kernel<<<node_feat_blocks, threads>>>(batch);
    final_kernel<<<N_GRAPHS, OUTF>>>(Wf, bf, out);
}

// round 4
// speedup vs baseline: 1.1957x; 1.1957x over previous
#include <cuda_runtime.h>
#include <cuda_bf16.h>
#include <mma.h>
#include <math.h>
#include <cstdint>

using namespace nvcuda;

#define N_NODES  50000
#define N_PAD    (N_NODES + 64)        // padded rows so wmma stores never fault
#define N_EDGES  800000
#define E_TOT    (N_EDGES + N_NODES)   // self-loops appended
#define N_GRAPHS 256
#define FEAT     128
#define HID      64
#define HEADS    4
#define HH       (HID*HEADS)           // 256
#define OUTF     128
#define NEG_SLOPE 0.2f

#define TILE_M   64                     // GEMM CTA tile rows

// ---------------- scratch (device globals; no allocs allowed) ----------------
__device__ float g_h[(size_t)N_PAD*HH];       // GEMM output (per-layer features)
__device__ float g_x[(size_t)N_NODES*HH];     // aggregation output -> next layer input
__device__ __nv_bfloat16 g_xb_hi[(size_t)N_PAD*HH];  // bf16-split GEMM input
__device__ __nv_bfloat16 g_xb_lo[(size_t)N_PAD*HH];
__device__ __nv_bfloat16 g_wb_hi[HH*HH];      // bf16-split W, layout [n][k], row stride 256
__device__ __nv_bfloat16 g_wb_lo[HH*HH];
__device__ float g_as[N_NODES*HEADS];
__device__ float g_ad[N_NODES*HEADS];
__device__ float g_m[N_NODES*HEADS];
__device__ float g_s[N_NODES*HEADS];
__device__ float g_e[(size_t)E_TOT*HEADS];
__device__ float g_pool[N_GRAPHS*HH];
__device__ float g_cnt[N_GRAPHS];

// ---------------- misc helpers ----------------
__device__ __forceinline__ void atomicMaxF(float* addr, float val) {
    int* ai = (int*)addr;
    int old = *ai;
    while (__int_as_float(old) < val) {
        int prev = atomicCAS(ai, old, __float_as_int(val));
        if (prev == old) break;
        old = prev;
    }
}
__device__ __forceinline__ void edge_src_dst(int e, const int* ei, int& src, int& dst) {
    if (e < N_EDGES) { src = ei[e]; dst = ei[N_EDGES + e]; }
    else             { src = dst = e - N_EDGES; }
}
__device__ __forceinline__ void split2(float v, __nv_bfloat16& hi, __nv_bfloat16& lo) {
    hi = __float2bfloat16(v);
    lo = __float2bfloat16(v - __bfloat162float(hi));
}

// ---------------- prep kernels ----------------
// W [K, 256] row-major  ->  g_wb [n][k] (row stride 256), split hi/lo
__global__ void prep_w_kernel(const float* __restrict__ W, int K) {
    int idx = blockIdx.x * blockDim.x + threadIdx.x;
    if (idx >= K * HH) return;
    int k = idx >> 8, n = idx & (HH - 1);
    __nv_bfloat16 hi, lo;
    split2(W[idx], hi, lo);
    g_wb_hi[n * HH + k] = hi;
    g_wb_lo[n * HH + k] = lo;
}
// layer-0 input x [N, 128] -> bf16 splits (row stride 128 = K); zero-pad tail rows
__global__ void prep_x0_kernel(const float* __restrict__ x) {
    int idx = blockIdx.x * blockDim.x + threadIdx.x;
    if (idx >= N_PAD * FEAT) return;
    float v = (idx < N_NODES * FEAT) ? x[idx] : 0.f;
    __nv_bfloat16 hi, lo;
    split2(v, hi, lo);
    g_xb_hi[idx] = hi;
    g_xb_lo[idx] = lo;
}

// ---------------- tensor-core (HMMA/wmma) GEMM + fused alphas ----------------
// C[64,256] = A[64,K] @ W[K,256]; bf16 hi/lo 3-term split; fp32 accum.
// 8 warps: warp tile 32 rows x 64 cols (mw = wid&1, nw = wid>>1).
#define LDP 24   // padded smem leading dim (elems) to spread ldmatrix banks
__global__ __launch_bounds__(256)
void gat_gemm_kernel(const float* __restrict__ a_s, const float* __restrict__ a_d,
                     int K) {
    __shared__ __nv_bfloat16 As_hi[TILE_M * LDP];
    __shared__ __nv_bfloat16 As_lo[TILE_M * LDP];
    __shared__ __nv_bfloat16 Bs_hi[HH * LDP];
    __shared__ __nv_bfloat16 Bs_lo[HH * LDP];
    __shared__ float as_sh[HH], ad_sh[HH];

    const int tid = threadIdx.x;
    const int wid = tid >> 5;
    const int mw  = wid & 1;       // 0..1   (rows)
    const int nw  = wid >> 1;      // 0..3   (cols)
    const int rowBase = blockIdx.x * TILE_M;

    for (int i = tid; i < HH; i += 256) { as_sh[i] = a_s[i]; ad_sh[i] = a_d[i]; }

    wmma::fragment<wmma::accumulator, 16, 16, 16, float> acc[2][4];
    #pragma unroll
    for (int i = 0; i < 2; i++)
        #pragma unroll
        for (int j = 0; j < 4; j++)
            wmma::fill_fragment(acc[i][j], 0.f);

    for (int k0 = 0; k0 < K; k0 += 16) {
        // stage A: 64 rows x 16 k (hi+lo). 128 uint4 per matrix.
        if (tid < 128) {
            int r = tid >> 1, half = tid & 1;
            size_t gsrc = (size_t)(rowBase + r) * K + k0 + half * 8;
            uint4 vh = *(const uint4*)(g_xb_hi + gsrc);
            uint4 vl = *(const uint4*)(g_xb_lo + gsrc);
            *(uint4*)(As_hi + r * LDP + half * 8) = vh;
            *(uint4*)(As_lo + r * LDP + half * 8) = vl;
        }
        // stage B: 256 n-rows x 16 k (hi+lo). 512 uint4 per matrix; 2 per thread each.
        #pragma unroll
        for (int t = 0; t < 2; t++) {
            int i = tid + t * 256;         // 0..511
            int n = i >> 1, half = i & 1;
            int gsrc = n * HH + k0 + half * 8;
            uint4 vh = *(const uint4*)(g_wb_hi + gsrc);
            uint4 vl = *(const uint4*)(g_wb_lo + gsrc);
            *(uint4*)(Bs_hi + n * LDP + half * 8) = vh;
            *(uint4*)(Bs_lo + n * LDP + half * 8) = vl;
        }
        __syncthreads();

        wmma::fragment<wmma::matrix_a, 16, 16, 16, __nv_bfloat16, wmma::row_major> a_hi[2], a_lo[2];
        #pragma unroll
        for (int i = 0; i < 2; i++) {
            const __nv_bfloat16* ap = As_hi + (mw * 32 + i * 16) * LDP;
            wmma::load_matrix_sync(a_hi[i], ap, LDP);
            wmma::load_matrix_sync(a_lo[i], As_lo + (mw * 32 + i * 16) * LDP, LDP);
        }
        #pragma unroll
        for (int j = 0; j < 4; j++) {
            wmma::fragment<wmma::matrix_b, 16, 16, 16, __nv_bfloat16, wmma::col_major> b_hi, b_lo;
            wmma::load_matrix_sync(b_hi, Bs_hi + (nw * 64 + j * 16) * LDP, LDP);
            wmma::load_matrix_sync(b_lo, Bs_lo + (nw * 64 + j * 16) * LDP, LDP);
            #pragma unroll
            for (int i = 0; i < 2; i++) {
                wmma::mma_sync(acc[i][j], a_hi[i], b_hi, acc[i][j]);
                wmma::mma_sync(acc[i][j], a_hi[i], b_lo, acc[i][j]);
                wmma::mma_sync(acc[i][j], a_lo[i], b_hi, acc[i][j]);
            }
        }
        __syncthreads();
    }

    // store C tile to g_h (padded, so no row guard needed)
    #pragma unroll
    for (int i = 0; i < 2; i++)
        #pragma unroll
        for (int j = 0; j < 4; j++) {
            float* cp = g_h + (size_t)(rowBase + mw * 32 + i * 16) * HH + nw * 64 + j * 16;
            wmma::store_matrix_sync(cp, acc[i][j], HH, wmma::mem_row_major);
        }
    __syncthreads();   // make g_h tile visible to all warps in this CTA

    // fused alphas: thread -> (row = tid>>2, head = tid&3); 64-wide dot
    int r = rowBase + (tid >> 2);
    int hd = tid & 3;
    if (r < N_NODES) {
        const float* hp = g_h + (size_t)r * HH + hd * HID;
        const float* sp = as_sh + hd * HID;
        const float* dp = ad_sh + hd * HID;
        float vs = 0.f, vd = 0.f;
        #pragma unroll
        for (int c = 0; c < HID; c += 4) {
            float4 v = *(const float4*)(hp + c);
            vs += v.x * sp[c] + v.y * sp[c+1] + v.z * sp[c+2] + v.w * sp[c+3];
            vd += v.x * dp[c] + v.y * dp[c+1] + v.z * dp[c+2] + v.w * dp[c+3];
        }
        g_as[r * HEADS + hd] = vs;
        g_ad[r * HEADS + hd] = vd;
    }
}

// ---------------- init m=-inf, s=0, x(agg target)=0 ----------------
__global__ void init_layer_kernel() {
    int idx = blockIdx.x * blockDim.x + threadIdx.x;
    if (idx < N_NODES * HH) g_x[idx] = 0.f;
    if (idx < N_NODES * HEADS) {
        g_m[idx] = -INFINITY;
        g_s[idx] = 0.f;
    }
}

// ---------------- pass A: e = leaky_relu(as[src]+ad[dst]); segment max ----------------
__global__ void edge_max_kernel(const int* __restrict__ ei) {
    int e = blockIdx.x * blockDim.x + threadIdx.x;
    if (e >= E_TOT) return;
    int src, dst;
    edge_src_dst(e, ei, src, dst);
    float4 vs = *(const float4*)(g_as + src * HEADS);
    float4 vd = *(const float4*)(g_ad + dst * HEADS);
    float v[4] = {vs.x + vd.x, vs.y + vd.y, vs.z + vd.z, vs.w + vd.w};
    #pragma unroll
    for (int h = 0; h < HEADS; h++) {
        v[h] = (v[h] > 0.f) ? v[h] : NEG_SLOPE * v[h];
        atomicMaxF(&g_m[dst * HEADS + h], v[h]);
    }
    *(float4*)(g_e + (size_t)e * HEADS) = make_float4(v[0], v[1], v[2], v[3]);
}

// ---------------- pass B: ex = exp(e - m[dst]); segment sum ----------------
__global__ void edge_exp_kernel(const int* __restrict__ ei) {
    int e = blockIdx.x * blockDim.x + threadIdx.x;
    if (e >= E_TOT) return;
    int src, dst;
    edge_src_dst(e, ei, src, dst);
    (void)src;
    float4 ev = *(const float4*)(g_e + (size_t)e * HEADS);
    float4 mv = *(const float4*)(g_m + dst * HEADS);
    float ex[4] = {expf(ev.x - mv.x), expf(ev.y - mv.y), expf(ev.z - mv.z), expf(ev.w - mv.w)};
    #pragma unroll
    for (int h = 0; h < HEADS; h++)
        atomicAdd(&g_s[dst * HEADS + h], ex[h]);
    *(float4*)(g_e + (size_t)e * HEADS) = make_float4(ex[0], ex[1], ex[2], ex[3]);
}

// ---------------- pass C: out[dst] += h[src] * alpha ----------------
__global__ void edge_agg_kernel(const int* __restrict__ ei) {
    int e = blockIdx.x * 8 + (threadIdx.x >> 5);
    int lane = threadIdx.x & 31;
    if (e >= E_TOT) return;
    int src, dst;
    edge_src_dst(e, ei, src, dst);

    float a = 0.f;
    if (lane < HEADS)
        a = g_e[(size_t)e * HEADS + lane] / g_s[dst * HEADS + lane];

    const float* hs = g_h + (size_t)src * HH;
    float* od = g_x + (size_t)dst * HH;
    #pragma unroll
    for (int j0 = 0; j0 < HH; j0 += 32) {
        int j = j0 + lane;
        float al = __shfl_sync(0xffffffffu, a, j >> 6);
        atomicAdd(&od[j], hs[j] * al);
    }
}

// ---------------- bias + ELU (in place on g_x) + bf16 split for next GEMM ----------------
__global__ void bias_elu_split_kernel(const float* __restrict__ b) {
    int idx = blockIdx.x * blockDim.x + threadIdx.x;
    if (idx >= N_PAD * HH) return;
    __nv_bfloat16 hi, lo;
    if (idx < N_NODES * HH) {
        float v = g_x[idx] + b[idx & (HH - 1)];
        float o = (v > 0.f) ? v : expm1f(v);
        g_x[idx] = o;
        split2(o, hi, lo);
    } else {
        hi = __float2bfloat16(0.f);
        lo = hi;
    }
    g_xb_hi[idx] = hi;
    g_xb_lo[idx] = lo;
}

// ---------------- pooling ----------------
__global__ void pool_zero_kernel() {
    int idx = blockIdx.x * blockDim.x + threadIdx.x;
    if (idx < N_GRAPHS * HH) g_pool[idx] = 0.f;
    if (idx < N_GRAPHS) g_cnt[idx] = 0.f;
}

__global__ void pool_kernel(const int* __restrict__ batch) {
    int idx = blockIdx.x * blockDim.x + threadIdx.x;
    if (idx >= N_NODES * HH) return;
    int n = idx >> 8;
    int f = idx & (HH - 1);
    int g = batch[n];
    atomicAdd(&g_pool[g * HH + f], g_x[idx]);
    if (f == 0) atomicAdd(&g_cnt[g], 1.0f);
}

// ---------------- final: y = (pool/cnt) @ Wf + bf; L2-normalize rows ----------------
__global__ void final_kernel(const float* __restrict__ Wf, const float* __restrict__ bf,
                             float* __restrict__ out) {
    __shared__ float gs[HH];
    __shared__ float red[OUTF];
    int g = blockIdx.x;
    int t = threadIdx.x;
    float cnt = fmaxf(g_cnt[g], 1.0f);
    for (int i = t; i < HH; i += OUTF) gs[i] = g_pool[g * HH + i] / cnt;
    __syncthreads();
    float acc = bf[t];
    #pragma unroll 8
    for (int k = 0; k < HH; k++)
        acc += gs[k] * Wf[(size_t)k * OUTF + t];
    red[t] = acc * acc;
    __syncthreads();
    #pragma unroll
    for (int off = 64; off > 0; off >>= 1) {
        if (t < off) red[t] += red[t + off];
        __syncthreads();
    }
    float norm = fmaxf(sqrtf(red[0]), 1e-12f);
    out[(size_t)g * OUTF + t] = acc / norm;
}

// ---------------- host orchestration ----------------
extern "C" void kernel_launch(void* const* d_in, const int* in_sizes, int n_in,
                              void* d_out, int out_size) {
    const float* x     = (const float*)d_in[0];
    const int*   ei    = (const int*)d_in[1];
    const int*   batch = (const int*)d_in[2];
    const float* W[3]  = {(const float*)d_in[3],  (const float*)d_in[7],  (const float*)d_in[11]};
    const float* AS[3] = {(const float*)d_in[4],  (const float*)d_in[8],  (const float*)d_in[12]};
    const float* AD[3] = {(const float*)d_in[5],  (const float*)d_in[9],  (const float*)d_in[13]};
    const float* Bb[3] = {(const float*)d_in[6],  (const float*)d_in[10], (const float*)d_in[14]};
    const float* Wf = (const float*)d_in[15];
    const float* bf = (const float*)d_in[16];
    float* out = (float*)d_out;

    const int threads = 256;
    const int edge_blocks      = (E_TOT + threads - 1) / threads;
    const int edge_warp_blocks = (E_TOT + 7) / 8;
    const int node_feat_blocks = (N_NODES * HH + threads - 1) / threads;
    const int node_pad_blocks  = (N_PAD * HH + threads - 1) / threads;
    const int gemm_blocks      = (N_NODES + TILE_M - 1) / TILE_M;

    prep_x0_kernel<<<(N_PAD * FEAT + threads - 1) / threads, threads>>>(x);

    int Din = FEAT;
    for (int l = 0; l < 3; l++) {
        prep_w_kernel<<<(Din * HH + threads - 1) / threads, threads>>>(W[l], Din);
        gat_gemm_kernel<<<gemm_blocks, 256>>>(AS[l], AD[l], Din);
        init_layer_kernel<<<node_feat_blocks, threads>>>();
        edge_max_kernel<<<edge_blocks, threads>>>(ei);
        edge_exp_kernel<<<edge_blocks, threads>>>(ei);
        edge_agg_kernel<<<edge_warp_blocks, 256>>>(ei);
        bias_elu_split_kernel<<<node_pad_blocks, threads>>>(Bb[l]);
        Din = HH;
    }

    pool_zero_kernel<<<(N_GRAPHS * HH + threads - 1) / threads, threads>>>();
    pool_kernel<<<node_feat_blocks, threads>>>(batch);
    final_kernel<<<N_GRAPHS, OUTF>>>(Wf, bf, out);
}

// round 5
// speedup vs baseline: 1.8725x; 1.5661x over previous
#include <cuda_runtime.h>
#include <cuda_bf16.h>
#include <mma.h>
#include <math.h>
#include <cstdint>

using namespace nvcuda;

#define N_NODES  50000
#define N_PAD    (N_NODES + 64)
#define N_EDGES  800000
#define E_TOT    (N_EDGES + N_NODES)   // self-loops appended
#define N_GRAPHS 256
#define FEAT     128
#define HID      64
#define HEADS    4
#define HH       (HID*HEADS)           // 256
#define OUTF     128
#define NEG_SLOPE 0.2f

#define TILE_M   64

// ---------------- scratch (device globals; zero-initialized at load) ----------------
__device__ float g_h[(size_t)N_PAD*HH];
__device__ float g_x[(size_t)N_NODES*HH];            // only layer-3 output (for pool)
__device__ __nv_bfloat16 g_xb_hi[(size_t)N_PAD*HH];
__device__ __nv_bfloat16 g_xb_lo[(size_t)N_PAD*HH];
__device__ __nv_bfloat16 g_wb_hi[HH*HH];
__device__ __nv_bfloat16 g_wb_lo[HH*HH];
__device__ float g_as[N_NODES*HEADS];
__device__ float g_ad[N_NODES*HEADS];
__device__ float g_pool[N_GRAPHS*HH];
__device__ float g_cnt[N_GRAPHS];
// CSR (dst-sorted), built once per launch
__device__ int g_deg[N_NODES];
__device__ int g_rowptr[N_NODES+1];
__device__ int g_fill[N_NODES];
__device__ int g_colidx[E_TOT];     // src node per CSR slot

// ---------------- helpers ----------------
__device__ __forceinline__ void split2(float v, __nv_bfloat16& hi, __nv_bfloat16& lo) {
    hi = __float2bfloat16(v);
    lo = __float2bfloat16(v - __bfloat162float(hi));
}

// ---------------- prep kernels ----------------
__global__ void prep_w_kernel(const float* __restrict__ W, int K) {
    int idx = blockIdx.x * blockDim.x + threadIdx.x;
    if (idx >= K * HH) return;
    int k = idx >> 8, n = idx & (HH - 1);
    __nv_bfloat16 hi, lo;
    split2(W[idx], hi, lo);
    g_wb_hi[n * HH + k] = hi;
    g_wb_lo[n * HH + k] = lo;
}
__global__ void prep_x0_kernel(const float* __restrict__ x) {
    int idx = blockIdx.x * blockDim.x + threadIdx.x;
    if (idx >= N_PAD * FEAT) return;
    float v = (idx < N_NODES * FEAT) ? x[idx] : 0.f;
    __nv_bfloat16 hi, lo;
    split2(v, hi, lo);
    g_xb_hi[idx] = hi;
    g_xb_lo[idx] = lo;
}

// ---------------- CSR build (once per launch) ----------------
__global__ void csr_zero_kernel() {
    int i = blockIdx.x * blockDim.x + threadIdx.x;
    if (i < N_NODES) g_deg[i] = 0;
}
__global__ void csr_hist_kernel(const int* __restrict__ ei) {
    int e = blockIdx.x * blockDim.x + threadIdx.x;
    if (e >= E_TOT) return;
    int dst = (e < N_EDGES) ? ei[N_EDGES + e] : e - N_EDGES;
    atomicAdd(&g_deg[dst], 1);
}
__global__ void csr_scan_kernel() {   // single block, 1024 threads
    __shared__ int buf[1024];
    __shared__ int carry_sh;
    int tid = threadIdx.x;
    if (tid == 0) { carry_sh = 0; g_rowptr[0] = 0; }
    __syncthreads();
    for (int base = 0; base < N_NODES; base += 1024) {
        int v = (base + tid < N_NODES) ? g_deg[base + tid] : 0;
        buf[tid] = v;
        __syncthreads();
        #pragma unroll
        for (int off = 1; off < 1024; off <<= 1) {
            int t = (tid >= off) ? buf[tid - off] : 0;
            __syncthreads();
            buf[tid] += t;
            __syncthreads();
        }
        int incl = buf[tid] + carry_sh;
        if (base + tid < N_NODES) {
            g_rowptr[base + tid + 1] = incl;
            g_fill[base + tid] = incl - v;
        }
        __syncthreads();
        if (tid == 1023) carry_sh = incl;
        __syncthreads();
    }
}
__global__ void csr_scatter_kernel(const int* __restrict__ ei) {
    int e = blockIdx.x * blockDim.x + threadIdx.x;
    if (e >= E_TOT) return;
    int src, dst;
    if (e < N_EDGES) { src = ei[e]; dst = ei[N_EDGES + e]; }
    else             { src = dst = e - N_EDGES; }
    int pos = atomicAdd(&g_fill[dst], 1);
    g_colidx[pos] = src;
}

// ---------------- tensor-core GEMM + fused alphas (unchanged from R4) ----------------
#define LDP 24
__global__ __launch_bounds__(256)
void gat_gemm_kernel(const float* __restrict__ a_s, const float* __restrict__ a_d,
                     int K) {
    __shared__ __nv_bfloat16 As_hi[TILE_M * LDP];
    __shared__ __nv_bfloat16 As_lo[TILE_M * LDP];
    __shared__ __nv_bfloat16 Bs_hi[HH * LDP];
    __shared__ __nv_bfloat16 Bs_lo[HH * LDP];
    __shared__ float as_sh[HH], ad_sh[HH];

    const int tid = threadIdx.x;
    const int wid = tid >> 5;
    const int mw  = wid & 1;
    const int nw  = wid >> 1;
    const int rowBase = blockIdx.x * TILE_M;

    for (int i = tid; i < HH; i += 256) { as_sh[i] = a_s[i]; ad_sh[i] = a_d[i]; }

    wmma::fragment<wmma::accumulator, 16, 16, 16, float> acc[2][4];
    #pragma unroll
    for (int i = 0; i < 2; i++)
        #pragma unroll
        for (int j = 0; j < 4; j++)
            wmma::fill_fragment(acc[i][j], 0.f);

    for (int k0 = 0; k0 < K; k0 += 16) {
        if (tid < 128) {
            int r = tid >> 1, half = tid & 1;
            size_t gsrc = (size_t)(rowBase + r) * K + k0 + half * 8;
            uint4 vh = *(const uint4*)(g_xb_hi + gsrc);
            uint4 vl = *(const uint4*)(g_xb_lo + gsrc);
            *(uint4*)(As_hi + r * LDP + half * 8) = vh;
            *(uint4*)(As_lo + r * LDP + half * 8) = vl;
        }
        #pragma unroll
        for (int t = 0; t < 2; t++) {
            int i = tid + t * 256;
            int n = i >> 1, half = i & 1;
            int gsrc = n * HH + k0 + half * 8;
            uint4 vh = *(const uint4*)(g_wb_hi + gsrc);
            uint4 vl = *(const uint4*)(g_wb_lo + gsrc);
            *(uint4*)(Bs_hi + n * LDP + half * 8) = vh;
            *(uint4*)(Bs_lo + n * LDP + half * 8) = vl;
        }
        __syncthreads();

        wmma::fragment<wmma::matrix_a, 16, 16, 16, __nv_bfloat16, wmma::row_major> a_hi[2], a_lo[2];
        #pragma unroll
        for (int i = 0; i < 2; i++) {
            wmma::load_matrix_sync(a_hi[i], As_hi + (mw * 32 + i * 16) * LDP, LDP);
            wmma::load_matrix_sync(a_lo[i], As_lo + (mw * 32 + i * 16) * LDP, LDP);
        }
        #pragma unroll
        for (int j = 0; j < 4; j++) {
            wmma::fragment<wmma::matrix_b, 16, 16, 16, __nv_bfloat16, wmma::col_major> b_hi, b_lo;
            wmma::load_matrix_sync(b_hi, Bs_hi + (nw * 64 + j * 16) * LDP, LDP);
            wmma::load_matrix_sync(b_lo, Bs_lo + (nw * 64 + j * 16) * LDP, LDP);
            #pragma unroll
            for (int i = 0; i < 2; i++) {
                wmma::mma_sync(acc[i][j], a_hi[i], b_hi, acc[i][j]);
                wmma::mma_sync(acc[i][j], a_hi[i], b_lo, acc[i][j]);
                wmma::mma_sync(acc[i][j], a_lo[i], b_hi, acc[i][j]);
            }
        }
        __syncthreads();
    }

    #pragma unroll
    for (int i = 0; i < 2; i++)
        #pragma unroll
        for (int j = 0; j < 4; j++) {
            float* cp = g_h + (size_t)(rowBase + mw * 32 + i * 16) * HH + nw * 64 + j * 16;
            wmma::store_matrix_sync(cp, acc[i][j], HH, wmma::mem_row_major);
        }
    __syncthreads();

    int r = rowBase + (tid >> 2);
    int hd = tid & 3;
    if (r < N_NODES) {
        const float* hp = g_h + (size_t)r * HH + hd * HID;
        const float* sp = as_sh + hd * HID;
        const float* dp = ad_sh + hd * HID;
        float vs = 0.f, vd = 0.f;
        #pragma unroll
        for (int c = 0; c < HID; c += 4) {
            float4 v = *(const float4*)(hp + c);
            vs += v.x * sp[c] + v.y * sp[c+1] + v.z * sp[c+2] + v.w * sp[c+3];
            vd += v.x * dp[c] + v.y * dp[c+1] + v.z * dp[c+2] + v.w * dp[c+3];
        }
        g_as[r * HEADS + hd] = vs;
        g_ad[r * HEADS + hd] = vd;
    }
}

// ---------------- fused per-node softmax + aggregation + bias + ELU + split ----------------
// One block (256 threads) per destination node. No atomics.
#define CHUNK 256
__global__ __launch_bounds__(256)
void agg_kernel(const float* __restrict__ bias, int last) {
    const int node = blockIdx.x;
    const int tid  = threadIdx.x;
    const int head = tid >> 6;          // feature column tid -> head
    const int lane = tid & 31;
    const int wrp  = tid >> 5;

    __shared__ float s_alpha[CHUNK * 4];
    __shared__ int   s_src[CHUNK];
    __shared__ float s_red[8 * 4];
    __shared__ float s_m[4], s_rs[4];

    const int start = g_rowptr[node];
    const int end   = g_rowptr[node + 1];

    const float4 ad4 = *(const float4*)(g_ad + node * HEADS);

    // --- phase A1: per-head max of leaky(as[src] + ad[dst]) ---
    float mx0 = -INFINITY, mx1 = -INFINITY, mx2 = -INFINITY, mx3 = -INFINITY;
    for (int i = start + tid; i < end; i += 256) {
        int s = g_colidx[i];
        float4 as4 = *(const float4*)(g_as + s * HEADS);
        float e0 = as4.x + ad4.x; e0 = (e0 > 0.f) ? e0 : NEG_SLOPE * e0;
        float e1 = as4.y + ad4.y; e1 = (e1 > 0.f) ? e1 : NEG_SLOPE * e1;
        float e2 = as4.z + ad4.z; e2 = (e2 > 0.f) ? e2 : NEG_SLOPE * e2;
        float e3 = as4.w + ad4.w; e3 = (e3 > 0.f) ? e3 : NEG_SLOPE * e3;
        mx0 = fmaxf(mx0, e0); mx1 = fmaxf(mx1, e1);
        mx2 = fmaxf(mx2, e2); mx3 = fmaxf(mx3, e3);
    }
    #pragma unroll
    for (int off = 16; off > 0; off >>= 1) {
        mx0 = fmaxf(mx0, __shfl_xor_sync(0xffffffffu, mx0, off));
        mx1 = fmaxf(mx1, __shfl_xor_sync(0xffffffffu, mx1, off));
        mx2 = fmaxf(mx2, __shfl_xor_sync(0xffffffffu, mx2, off));
        mx3 = fmaxf(mx3, __shfl_xor_sync(0xffffffffu, mx3, off));
    }
    if (lane == 0) {
        s_red[wrp * 4 + 0] = mx0; s_red[wrp * 4 + 1] = mx1;
        s_red[wrp * 4 + 2] = mx2; s_red[wrp * 4 + 3] = mx3;
    }
    __syncthreads();
    if (tid < 4) {
        float r = s_red[tid];
        #pragma unroll
        for (int w = 1; w < 8; w++) r = fmaxf(r, s_red[w * 4 + tid]);
        s_m[tid] = r;
    }
    __syncthreads();
    const float m0 = s_m[0], m1 = s_m[1], m2 = s_m[2], m3 = s_m[3];

    // --- phase A2: per-head sum of exp(e - m) ---
    float sm0 = 0.f, sm1 = 0.f, sm2 = 0.f, sm3 = 0.f;
    for (int i = start + tid; i < end; i += 256) {
        int s = g_colidx[i];
        float4 as4 = *(const float4*)(g_as + s * HEADS);
        float e0 = as4.x + ad4.x; e0 = (e0 > 0.f) ? e0 : NEG_SLOPE * e0;
        float e1 = as4.y + ad4.y; e1 = (e1 > 0.f) ? e1 : NEG_SLOPE * e1;
        float e2 = as4.z + ad4.z; e2 = (e2 > 0.f) ? e2 : NEG_SLOPE * e2;
        float e3 = as4.w + ad4.w; e3 = (e3 > 0.f) ? e3 : NEG_SLOPE * e3;
        sm0 += expf(e0 - m0); sm1 += expf(e1 - m1);
        sm2 += expf(e2 - m2); sm3 += expf(e3 - m3);
    }
    #pragma unroll
    for (int off = 16; off > 0; off >>= 1) {
        sm0 += __shfl_xor_sync(0xffffffffu, sm0, off);
        sm1 += __shfl_xor_sync(0xffffffffu, sm1, off);
        sm2 += __shfl_xor_sync(0xffffffffu, sm2, off);
        sm3 += __shfl_xor_sync(0xffffffffu, sm3, off);
    }
    __syncthreads();
    if (lane == 0) {
        s_red[wrp * 4 + 0] = sm0; s_red[wrp * 4 + 1] = sm1;
        s_red[wrp * 4 + 2] = sm2; s_red[wrp * 4 + 3] = sm3;
    }
    __syncthreads();
    if (tid < 4) {
        float r = s_red[tid];
        #pragma unroll
        for (int w = 1; w < 8; w++) r += s_red[w * 4 + tid];
        s_rs[tid] = 1.f / r;
    }
    __syncthreads();
    const float rs0 = s_rs[0], rs1 = s_rs[1], rs2 = s_rs[2], rs3 = s_rs[3];

    // --- phase B: acc[f] = sum_e alpha_e[head(f)] * h[src_e][f] ---
    float acc = 0.f;
    for (int c0 = start; c0 < end; c0 += CHUNK) {
        int len = min(CHUNK, end - c0);
        for (int i = tid; i < len; i += 256) {
            int s = g_colidx[c0 + i];
            s_src[i] = s;
            float4 as4 = *(const float4*)(g_as + s * HEADS);
            float e0 = as4.x + ad4.x; e0 = (e0 > 0.f) ? e0 : NEG_SLOPE * e0;
            float e1 = as4.y + ad4.y; e1 = (e1 > 0.f) ? e1 : NEG_SLOPE * e1;
            float e2 = as4.z + ad4.z; e2 = (e2 > 0.f) ? e2 : NEG_SLOPE * e2;
            float e3 = as4.w + ad4.w; e3 = (e3 > 0.f) ? e3 : NEG_SLOPE * e3;
            s_alpha[i * 4 + 0] = expf(e0 - m0) * rs0;
            s_alpha[i * 4 + 1] = expf(e1 - m1) * rs1;
            s_alpha[i * 4 + 2] = expf(e2 - m2) * rs2;
            s_alpha[i * 4 + 3] = expf(e3 - m3) * rs3;
        }
        __syncthreads();
        for (int j = 0; j < len; j++) {
            float a = s_alpha[j * 4 + head];
            acc += a * g_h[(size_t)s_src[j] * HH + tid];
        }
        __syncthreads();
    }

    // --- epilogue: bias + ELU + (split OR g_x store) ---
    float v = acc + bias[tid];
    float o = (v > 0.f) ? v : expm1f(v);
    size_t oi = (size_t)node * HH + tid;
    if (last) {
        g_x[oi] = o;
    } else {
        __nv_bfloat16 hi, lo;
        split2(o, hi, lo);
        g_xb_hi[oi] = hi;
        g_xb_lo[oi] = lo;
    }
}

// ---------------- pooling ----------------
__global__ void pool_zero_kernel() {
    int idx = blockIdx.x * blockDim.x + threadIdx.x;
    if (idx < N_GRAPHS * HH) g_pool[idx] = 0.f;
    if (idx < N_GRAPHS) g_cnt[idx] = 0.f;
}
__global__ void pool_kernel(const int* __restrict__ batch) {
    int idx = blockIdx.x * blockDim.x + threadIdx.x;
    if (idx >= N_NODES * HH) return;
    int n = idx >> 8;
    int f = idx & (HH - 1);
    int g = batch[n];
    atomicAdd(&g_pool[g * HH + f], g_x[idx]);
    if (f == 0) atomicAdd(&g_cnt[g], 1.0f);
}

// ---------------- final ----------------
__global__ void final_kernel(const float* __restrict__ Wf, const float* __restrict__ bf,
                             float* __restrict__ out) {
    __shared__ float gs[HH];
    __shared__ float red[OUTF];
    int g = blockIdx.x;
    int t = threadIdx.x;
    float cnt = fmaxf(g_cnt[g], 1.0f);
    for (int i = t; i < HH; i += OUTF) gs[i] = g_pool[g * HH + i] / cnt;
    __syncthreads();
    float acc = bf[t];
    #pragma unroll 8
    for (int k = 0; k < HH; k++)
        acc += gs[k] * Wf[(size_t)k * OUTF + t];
    red[t] = acc * acc;
    __syncthreads();
    #pragma unroll
    for (int off = 64; off > 0; off >>= 1) {
        if (t < off) red[t] += red[t + off];
        __syncthreads();
    }
    float norm = fmaxf(sqrtf(red[0]), 1e-12f);
    out[(size_t)g * OUTF + t] = acc / norm;
}

// ---------------- host orchestration ----------------
extern "C" void kernel_launch(void* const* d_in, const int* in_sizes, int n_in,
                              void* d_out, int out_size) {
    const float* x     = (const float*)d_in[0];
    const int*   ei    = (const int*)d_in[1];
    const int*   batch = (const int*)d_in[2];
    const float* W[3]  = {(const float*)d_in[3],  (const float*)d_in[7],  (const float*)d_in[11]};
    const float* AS[3] = {(const float*)d_in[4],  (const float*)d_in[8],  (const float*)d_in[12]};
    const float* AD[3] = {(const float*)d_in[5],  (const float*)d_in[9],  (const float*)d_in[13]};
    const float* Bb[3] = {(const float*)d_in[6],  (const float*)d_in[10], (const float*)d_in[14]};
    const float* Wf = (const float*)d_in[15];
    const float* bf = (const float*)d_in[16];
    float* out = (float*)d_out;

    const int threads = 256;
    const int edge_blocks = (E_TOT + threads - 1) / threads;
    const int gemm_blocks = (N_NODES + TILE_M - 1) / TILE_M;

    // CSR build (graph fixed across layers)
    csr_zero_kernel<<<(N_NODES + threads - 1) / threads, threads>>>();
    csr_hist_kernel<<<edge_blocks, threads>>>(ei);
    csr_scan_kernel<<<1, 1024>>>();
    csr_scatter_kernel<<<edge_blocks, threads>>>(ei);

    prep_x0_kernel<<<(N_PAD * FEAT + threads - 1) / threads, threads>>>(x);

    int Din = FEAT;
    for (int l = 0; l < 3; l++) {
        prep_w_kernel<<<(Din * HH + threads - 1) / threads, threads>>>(W[l], Din);
        gat_gemm_kernel<<<gemm_blocks, 256>>>(AS[l], AD[l], Din);
        agg_kernel<<<N_NODES, 256>>>(Bb[l], l == 2 ? 1 : 0);
        Din = HH;
    }

    pool_zero_kernel<<<(N_GRAPHS * HH + threads - 1) / threads, threads>>>();
    pool_kernel<<<(N_NODES * HH + threads - 1) / threads, threads>>>(batch);
    final_kernel<<<N_GRAPHS, OUTF>>>(Wf, bf, out);
}

// round 6
// speedup vs baseline: 1.9658x; 1.0498x over previous
#include <cuda_runtime.h>
#include <cuda_bf16.h>
#include <mma.h>
#include <math.h>
#include <cstdint>

using namespace nvcuda;

#define N_NODES  50000
#define N_PAD    (N_NODES + 64)
#define N_EDGES  800000
#define E_TOT    (N_EDGES + N_NODES)
#define N_GRAPHS 256
#define FEAT     128
#define HID      64
#define HEADS    4
#define HH       (HID*HEADS)           // 256
#define OUTF     128
#define NEG_SLOPE 0.2f

#define TILE_M   64

// ---------------- scratch ----------------
__device__ float g_h[(size_t)N_PAD*HH];
__device__ float g_x[(size_t)N_NODES*HH];
__device__ __nv_bfloat16 g_xb_hi[(size_t)N_PAD*HH];
__device__ __nv_bfloat16 g_xb_lo[(size_t)N_PAD*HH];
__device__ __nv_bfloat16 g_wb_hi[HH*HH];
__device__ __nv_bfloat16 g_wb_lo[HH*HH];
__device__ float g_as[N_NODES*HEADS];
__device__ float g_ad[N_NODES*HEADS];
__device__ float g_pool[N_GRAPHS*HH];
__device__ int g_gstart[N_GRAPHS+1];
// CSR
__device__ int g_deg[N_NODES];
__device__ int g_rowptr[N_NODES+1];
__device__ int g_fill[N_NODES];
__device__ int g_colidx[E_TOT];

// ---------------- helpers ----------------
__device__ __forceinline__ void split2(float v, __nv_bfloat16& hi, __nv_bfloat16& lo) {
    hi = __float2bfloat16(v);
    lo = __float2bfloat16(v - __bfloat162float(hi));
}

// ---------------- prep ----------------
__global__ void prep_w_kernel(const float* __restrict__ W, int K) {
    int idx = blockIdx.x * blockDim.x + threadIdx.x;
    if (idx >= K * HH) return;
    int k = idx >> 8, n = idx & (HH - 1);
    __nv_bfloat16 hi, lo;
    split2(W[idx], hi, lo);
    g_wb_hi[n * HH + k] = hi;
    g_wb_lo[n * HH + k] = lo;
}
__global__ void prep_x0_kernel(const float* __restrict__ x) {
    int idx = blockIdx.x * blockDim.x + threadIdx.x;
    if (idx >= N_PAD * FEAT) return;
    float v = (idx < N_NODES * FEAT) ? x[idx] : 0.f;
    __nv_bfloat16 hi, lo;
    split2(v, hi, lo);
    g_xb_hi[idx] = hi;
    g_xb_lo[idx] = lo;
}

// ---------------- CSR build ----------------
__global__ void csr_zero_kernel() {
    int i = blockIdx.x * blockDim.x + threadIdx.x;
    if (i < N_NODES) g_deg[i] = 0;
}
__global__ void csr_hist_kernel(const int* __restrict__ ei) {
    int e = blockIdx.x * blockDim.x + threadIdx.x;
    if (e >= E_TOT) return;
    int dst = (e < N_EDGES) ? ei[N_EDGES + e] : e - N_EDGES;
    atomicAdd(&g_deg[dst], 1);
}
__global__ void csr_scan_kernel() {
    __shared__ int buf[1024];
    __shared__ int carry_sh;
    int tid = threadIdx.x;
    if (tid == 0) { carry_sh = 0; g_rowptr[0] = 0; }
    __syncthreads();
    for (int base = 0; base < N_NODES; base += 1024) {
        int v = (base + tid < N_NODES) ? g_deg[base + tid] : 0;
        buf[tid] = v;
        __syncthreads();
        #pragma unroll
        for (int off = 1; off < 1024; off <<= 1) {
            int t = (tid >= off) ? buf[tid - off] : 0;
            __syncthreads();
            buf[tid] += t;
            __syncthreads();
        }
        int incl = buf[tid] + carry_sh;
        if (base + tid < N_NODES) {
            g_rowptr[base + tid + 1] = incl;
            g_fill[base + tid] = incl - v;
        }
        __syncthreads();
        if (tid == 1023) carry_sh = incl;
        __syncthreads();
    }
}
__global__ void csr_scatter_kernel(const int* __restrict__ ei) {
    int e = blockIdx.x * blockDim.x + threadIdx.x;
    if (e >= E_TOT) return;
    int src, dst;
    if (e < N_EDGES) { src = ei[e]; dst = ei[N_EDGES + e]; }
    else             { src = dst = e - N_EDGES; }
    int pos = atomicAdd(&g_fill[dst], 1);
    g_colidx[pos] = src;
}

// ---------------- tensor-core GEMM + fused alphas ----------------
#define LDP 24
__global__ __launch_bounds__(256)
void gat_gemm_kernel(const float* __restrict__ a_s, const float* __restrict__ a_d,
                     int K) {
    __shared__ __nv_bfloat16 As_hi[TILE_M * LDP];
    __shared__ __nv_bfloat16 As_lo[TILE_M * LDP];
    __shared__ __nv_bfloat16 Bs_hi[HH * LDP];
    __shared__ __nv_bfloat16 Bs_lo[HH * LDP];
    __shared__ float as_sh[HH], ad_sh[HH];

    const int tid = threadIdx.x;
    const int wid = tid >> 5;
    const int mw  = wid & 1;
    const int nw  = wid >> 1;
    const int rowBase = blockIdx.x * TILE_M;

    for (int i = tid; i < HH; i += 256) { as_sh[i] = a_s[i]; ad_sh[i] = a_d[i]; }

    wmma::fragment<wmma::accumulator, 16, 16, 16, float> acc[2][4];
    #pragma unroll
    for (int i = 0; i < 2; i++)
        #pragma unroll
        for (int j = 0; j < 4; j++)
            wmma::fill_fragment(acc[i][j], 0.f);

    for (int k0 = 0; k0 < K; k0 += 16) {
        if (tid < 128) {
            int r = tid >> 1, half = tid & 1;
            size_t gsrc = (size_t)(rowBase + r) * K + k0 + half * 8;
            uint4 vh = *(const uint4*)(g_xb_hi + gsrc);
            uint4 vl = *(const uint4*)(g_xb_lo + gsrc);
            *(uint4*)(As_hi + r * LDP + half * 8) = vh;
            *(uint4*)(As_lo + r * LDP + half * 8) = vl;
        }
        #pragma unroll
        for (int t = 0; t < 2; t++) {
            int i = tid + t * 256;
            int n = i >> 1, half = i & 1;
            int gsrc = n * HH + k0 + half * 8;
            uint4 vh = *(const uint4*)(g_wb_hi + gsrc);
            uint4 vl = *(const uint4*)(g_wb_lo + gsrc);
            *(uint4*)(Bs_hi + n * LDP + half * 8) = vh;
            *(uint4*)(Bs_lo + n * LDP + half * 8) = vl;
        }
        __syncthreads();

        wmma::fragment<wmma::matrix_a, 16, 16, 16, __nv_bfloat16, wmma::row_major> a_hi[2], a_lo[2];
        #pragma unroll
        for (int i = 0; i < 2; i++) {
            wmma::load_matrix_sync(a_hi[i], As_hi + (mw * 32 + i * 16) * LDP, LDP);
            wmma::load_matrix_sync(a_lo[i], As_lo + (mw * 32 + i * 16) * LDP, LDP);
        }
        #pragma unroll
        for (int j = 0; j < 4; j++) {
            wmma::fragment<wmma::matrix_b, 16, 16, 16, __nv_bfloat16, wmma::col_major> b_hi, b_lo;
            wmma::load_matrix_sync(b_hi, Bs_hi + (nw * 64 + j * 16) * LDP, LDP);
            wmma::load_matrix_sync(b_lo, Bs_lo + (nw * 64 + j * 16) * LDP, LDP);
            #pragma unroll
            for (int i = 0; i < 2; i++) {
                wmma::mma_sync(acc[i][j], a_hi[i], b_hi, acc[i][j]);
                wmma::mma_sync(acc[i][j], a_hi[i], b_lo, acc[i][j]);
                wmma::mma_sync(acc[i][j], a_lo[i], b_hi, acc[i][j]);
            }
        }
        __syncthreads();
    }

    #pragma unroll
    for (int i = 0; i < 2; i++)
        #pragma unroll
        for (int j = 0; j < 4; j++) {
            float* cp = g_h + (size_t)(rowBase + mw * 32 + i * 16) * HH + nw * 64 + j * 16;
            wmma::store_matrix_sync(cp, acc[i][j], HH, wmma::mem_row_major);
        }
    __syncthreads();

    int r = rowBase + (tid >> 2);
    int hd = tid & 3;
    if (r < N_NODES) {
        const float* hp = g_h + (size_t)r * HH + hd * HID;
        const float* sp = as_sh + hd * HID;
        const float* dp = ad_sh + hd * HID;
        float vs = 0.f, vd = 0.f;
        #pragma unroll
        for (int c = 0; c < HID; c += 4) {
            float4 v = *(const float4*)(hp + c);
            vs += v.x * sp[c] + v.y * sp[c+1] + v.z * sp[c+2] + v.w * sp[c+3];
            vd += v.x * dp[c] + v.y * dp[c+1] + v.z * dp[c+2] + v.w * dp[c+3];
        }
        g_as[r * HEADS + hd] = vs;
        g_ad[r * HEADS + hd] = vd;
    }
}

// ---------------- fused single-pass (flash) softmax + aggregation + epilogue ----------------
// One block (256 threads) per destination node. Running (m, s) with acc rescale per chunk.
// Phase B: 2 edges in flight (eh = tid>>7) x 128 float2 feature-pairs (fp = tid&127).
#define ACHUNK 256
__global__ __launch_bounds__(256)
void agg_kernel(const float* __restrict__ bias, int last) {
    const int node = blockIdx.x;
    const int tid  = threadIdx.x;
    const int lane = tid & 31;
    const int wrp  = tid >> 5;
    const int eh   = tid >> 7;        // edge parity
    const int fp   = tid & 127;       // feature pair index
    const int hfp  = fp >> 5;         // head of this feature pair

    __shared__ int   s_src[ACHUNK];
    __shared__ float s_al[ACHUNK * 4];
    __shared__ float s_red[8 * 4];
    __shared__ float s_m[4], s_s[4], s_scale[4];
    __shared__ float s_comb[128 * 2];

    const int start = g_rowptr[node];
    const int end   = g_rowptr[node + 1];

    const float4 ad4 = *(const float4*)(g_ad + node * HEADS);

    if (tid < 4) { s_m[tid] = -INFINITY; s_s[tid] = 0.f; }
    float accx = 0.f, accy = 0.f;
    __syncthreads();

    for (int c0 = start; c0 < end; c0 += ACHUNK) {
        const int len = min(ACHUNK, end - c0);
        const bool have = (tid < len);

        // 1) gather + raw logits
        float e0 = -INFINITY, e1 = -INFINITY, e2 = -INFINITY, e3 = -INFINITY;
        if (have) {
            int s = g_colidx[c0 + tid];
            s_src[tid] = s;
            float4 as4 = *(const float4*)(g_as + s * HEADS);
            e0 = as4.x + ad4.x; e0 = (e0 > 0.f) ? e0 : NEG_SLOPE * e0;
            e1 = as4.y + ad4.y; e1 = (e1 > 0.f) ? e1 : NEG_SLOPE * e1;
            e2 = as4.z + ad4.z; e2 = (e2 > 0.f) ? e2 : NEG_SLOPE * e2;
            e3 = as4.w + ad4.w; e3 = (e3 > 0.f) ? e3 : NEG_SLOPE * e3;
            s_al[tid * 4 + 0] = e0; s_al[tid * 4 + 1] = e1;
            s_al[tid * 4 + 2] = e2; s_al[tid * 4 + 3] = e3;
        }
        // 2) chunk max per head
        float m0 = e0, m1 = e1, m2 = e2, m3 = e3;
        #pragma unroll
        for (int off = 16; off > 0; off >>= 1) {
            m0 = fmaxf(m0, __shfl_xor_sync(0xffffffffu, m0, off));
            m1 = fmaxf(m1, __shfl_xor_sync(0xffffffffu, m1, off));
            m2 = fmaxf(m2, __shfl_xor_sync(0xffffffffu, m2, off));
            m3 = fmaxf(m3, __shfl_xor_sync(0xffffffffu, m3, off));
        }
        if (lane == 0) {
            s_red[wrp * 4 + 0] = m0; s_red[wrp * 4 + 1] = m1;
            s_red[wrp * 4 + 2] = m2; s_red[wrp * 4 + 3] = m3;
        }
        __syncthreads();
        // 3) update running max + rescale factor
        if (tid < 4) {
            float cm = s_red[tid];
            #pragma unroll
            for (int w = 1; w < 8; w++) cm = fmaxf(cm, s_red[w * 4 + tid]);
            float om = s_m[tid];
            float nm = fmaxf(om, cm);
            s_scale[tid] = expf(om - nm);      // exp(-inf)=0 handles first chunk
            s_m[tid] = nm;
        }
        __syncthreads();
        // 4) rescale acc; compute unnormalized alphas + chunk sums
        float sc = s_scale[hfp];
        accx *= sc; accy *= sc;
        float q0 = 0.f, q1 = 0.f, q2 = 0.f, q3 = 0.f;
        if (have) {
            q0 = expf(s_al[tid * 4 + 0] - s_m[0]); s_al[tid * 4 + 0] = q0;
            q1 = expf(s_al[tid * 4 + 1] - s_m[1]); s_al[tid * 4 + 1] = q1;
            q2 = expf(s_al[tid * 4 + 2] - s_m[2]); s_al[tid * 4 + 2] = q2;
            q3 = expf(s_al[tid * 4 + 3] - s_m[3]); s_al[tid * 4 + 3] = q3;
        }
        #pragma unroll
        for (int off = 16; off > 0; off >>= 1) {
            q0 += __shfl_xor_sync(0xffffffffu, q0, off);
            q1 += __shfl_xor_sync(0xffffffffu, q1, off);
            q2 += __shfl_xor_sync(0xffffffffu, q2, off);
            q3 += __shfl_xor_sync(0xffffffffu, q3, off);
        }
        __syncthreads();   // s_red free again
        if (lane == 0) {
            s_red[wrp * 4 + 0] = q0; s_red[wrp * 4 + 1] = q1;
            s_red[wrp * 4 + 2] = q2; s_red[wrp * 4 + 3] = q3;
        }
        __syncthreads();
        if (tid < 4) {
            float cs = s_red[tid];
            #pragma unroll
            for (int w = 1; w < 8; w++) cs += s_red[w * 4 + tid];
            s_s[tid] = s_s[tid] * s_scale[tid] + cs;
        }
        // 5) phase B: weighted gather of h rows (2 edges in flight)
        #pragma unroll 4
        for (int j = eh; j < len; j += 2) {
            float2 hv = *(const float2*)(g_h + (size_t)s_src[j] * HH + fp * 2);
            float a = s_al[j * 4 + hfp];
            accx += a * hv.x;
            accy += a * hv.y;
        }
        __syncthreads();
    }

    // combine eh partials
    if (eh == 1) { s_comb[fp * 2] = accx; s_comb[fp * 2 + 1] = accy; }
    __syncthreads();
    if (eh == 0) {
        accx += s_comb[fp * 2];
        accy += s_comb[fp * 2 + 1];
        float rs = 1.f / s_s[hfp];
        int f0 = fp * 2;
        float v0 = accx * rs + bias[f0];
        float v1 = accy * rs + bias[f0 + 1];
        float o0 = (v0 > 0.f) ? v0 : expm1f(v0);
        float o1 = (v1 > 0.f) ? v1 : expm1f(v1);
        size_t oi = (size_t)node * HH + f0;
        if (last) {
            g_x[oi] = o0;
            g_x[oi + 1] = o1;
        } else {
            __nv_bfloat16 h0, l0, h1, l1;
            split2(o0, h0, l0);
            split2(o1, h1, l1);
            *(__nv_bfloat162*)(g_xb_hi + oi) = __nv_bfloat162(h0, h1);
            *(__nv_bfloat162*)(g_xb_lo + oi) = __nv_bfloat162(l0, l1);
        }
    }
}

// ---------------- pooling (batch is sorted -> contiguous ranges) ----------------
__global__ void graph_bounds_kernel(const int* __restrict__ batch) {
    int n = blockIdx.x * blockDim.x + threadIdx.x;
    if (n >= N_NODES) return;
    int b = batch[n];
    if (n == 0) {
        for (int g = 0; g <= b; g++) g_gstart[g] = 0;
    } else {
        int bp = batch[n - 1];
        for (int g = bp + 1; g <= b; g++) g_gstart[g] = n;
    }
    if (n == N_NODES - 1) {
        for (int g = b + 1; g <= N_GRAPHS; g++) g_gstart[g] = N_NODES;
    }
}
__global__ void pool_mean_kernel() {   // grid=N_GRAPHS, block=256
    int g = blockIdx.x, f = threadIdx.x;
    int s = g_gstart[g], e = g_gstart[g + 1];
    float acc = 0.f;
    for (int n = s; n < e; n++)
        acc += g_x[(size_t)n * HH + f];
    g_pool[g * HH + f] = acc / (float)max(e - s, 1);
}

// ---------------- final ----------------
__global__ void final_kernel(const float* __restrict__ Wf, const float* __restrict__ bf,
                             float* __restrict__ out) {
    __shared__ float gs[HH];
    __shared__ float red[OUTF];
    int g = blockIdx.x;
    int t = threadIdx.x;
    for (int i = t; i < HH; i += OUTF) gs[i] = g_pool[g * HH + i];
    __syncthreads();
    float acc = bf[t];
    #pragma unroll 8
    for (int k = 0; k < HH; k++)
        acc += gs[k] * Wf[(size_t)k * OUTF + t];
    red[t] = acc * acc;
    __syncthreads();
    #pragma unroll
    for (int off = 64; off > 0; off >>= 1) {
        if (t < off) red[t] += red[t + off];
        __syncthreads();
    }
    float norm = fmaxf(sqrtf(red[0]), 1e-12f);
    out[(size_t)g * OUTF + t] = acc / norm;
}

// ---------------- host orchestration ----------------
extern "C" void kernel_launch(void* const* d_in, const int* in_sizes, int n_in,
                              void* d_out, int out_size) {
    const float* x     = (const float*)d_in[0];
    const int*   ei    = (const int*)d_in[1];
    const int*   batch = (const int*)d_in[2];
    const float* W[3]  = {(const float*)d_in[3],  (const float*)d_in[7],  (const float*)d_in[11]};
    const float* AS[3] = {(const float*)d_in[4],  (const float*)d_in[8],  (const float*)d_in[12]};
    const float* AD[3] = {(const float*)d_in[5],  (const float*)d_in[9],  (const float*)d_in[13]};
    const float* Bb[3] = {(const float*)d_in[6],  (const float*)d_in[10], (const float*)d_in[14]};
    const float* Wf = (const float*)d_in[15];
    const float* bf = (const float*)d_in[16];
    float* out = (float*)d_out;

    const int threads = 256;
    const int edge_blocks = (E_TOT + threads - 1) / threads;
    const int gemm_blocks = (N_NODES + TILE_M - 1) / TILE_M;

    csr_zero_kernel<<<(N_NODES + threads - 1) / threads, threads>>>();
    csr_hist_kernel<<<edge_blocks, threads>>>(ei);
    csr_scan_kernel<<<1, 1024>>>();
    csr_scatter_kernel<<<edge_blocks, threads>>>(ei);
    graph_bounds_kernel<<<(N_NODES + threads - 1) / threads, threads>>>(batch);

    prep_x0_kernel<<<(N_PAD * FEAT + threads - 1) / threads, threads>>>(x);

    int Din = FEAT;
    for (int l = 0; l < 3; l++) {
        prep_w_kernel<<<(Din * HH + threads - 1) / threads, threads>>>(W[l], Din);
        gat_gemm_kernel<<<gemm_blocks, 256>>>(AS[l], AD[l], Din);
        agg_kernel<<<N_NODES, 256>>>(Bb[l], l == 2 ? 1 : 0);
        Din = HH;
    }

    pool_mean_kernel<<<N_GRAPHS, 256>>>();
    final_kernel<<<N_GRAPHS, OUTF>>>(Wf, bf, out);
}

// round 7
// speedup vs baseline: 2.7296x; 1.3885x over previous
#include <cuda_runtime.h>
#include <cuda_bf16.h>
#include <mma.h>
#include <math.h>
#include <cstdint>

using namespace nvcuda;

#define N_NODES  50000
#define N_PAD    (N_NODES + 64)
#define N_EDGES  800000
#define E_TOT    (N_EDGES + N_NODES)
#define N_GRAPHS 256
#define FEAT     128
#define HID      64
#define HEADS    4
#define HH       (HID*HEADS)           // 256
#define OUTF     128
#define NEG_SLOPE 0.2f

#define TILE_M   64

// ---------------- scratch ----------------
__device__ float g_h[(size_t)N_PAD*HH];
__device__ float g_x[(size_t)N_NODES*HH];
__device__ __nv_bfloat16 g_xb_hi[(size_t)N_PAD*HH];
__device__ __nv_bfloat16 g_xb_lo[(size_t)N_PAD*HH];
__device__ __nv_bfloat16 g_wb_hi[HH*HH];
__device__ __nv_bfloat16 g_wb_lo[HH*HH];
__device__ float g_as[N_NODES*HEADS];
__device__ float g_ad[N_NODES*HEADS];
__device__ float g_pool[N_GRAPHS*HH];
__device__ int g_gstart[N_GRAPHS+1];
// CSR
__device__ int g_deg[N_NODES];
__device__ int g_rowptr[N_NODES+1];
__device__ int g_fill[N_NODES];
__device__ int g_colidx[E_TOT];

// ---------------- helpers ----------------
__device__ __forceinline__ void split2(float v, __nv_bfloat16& hi, __nv_bfloat16& lo) {
    hi = __float2bfloat16(v);
    lo = __float2bfloat16(v - __bfloat162float(hi));
}
__device__ __forceinline__ float warp_max(float v) {
    #pragma unroll
    for (int off = 16; off > 0; off >>= 1)
        v = fmaxf(v, __shfl_xor_sync(0xffffffffu, v, off));
    return v;
}
__device__ __forceinline__ float warp_sum(float v) {
    #pragma unroll
    for (int off = 16; off > 0; off >>= 1)
        v += __shfl_xor_sync(0xffffffffu, v, off);
    return v;
}

// ---------------- prep ----------------
__global__ void prep_w_kernel(const float* __restrict__ W, int K) {
    int idx = blockIdx.x * blockDim.x + threadIdx.x;
    if (idx >= K * HH) return;
    int k = idx >> 8, n = idx & (HH - 1);
    __nv_bfloat16 hi, lo;
    split2(W[idx], hi, lo);
    g_wb_hi[n * HH + k] = hi;
    g_wb_lo[n * HH + k] = lo;
}
__global__ void prep_x0_kernel(const float* __restrict__ x) {
    int idx = blockIdx.x * blockDim.x + threadIdx.x;
    if (idx >= N_PAD * FEAT) return;
    float v = (idx < N_NODES * FEAT) ? x[idx] : 0.f;
    __nv_bfloat16 hi, lo;
    split2(v, hi, lo);
    g_xb_hi[idx] = hi;
    g_xb_lo[idx] = lo;
}

// ---------------- CSR build ----------------
__global__ void csr_zero_kernel() {
    int i = blockIdx.x * blockDim.x + threadIdx.x;
    if (i < N_NODES) g_deg[i] = 0;
}
__global__ void csr_hist_kernel(const int* __restrict__ ei) {
    int e = blockIdx.x * blockDim.x + threadIdx.x;
    if (e >= E_TOT) return;
    int dst = (e < N_EDGES) ? ei[N_EDGES + e] : e - N_EDGES;
    atomicAdd(&g_deg[dst], 1);
}
__global__ void csr_scan_kernel() {
    __shared__ int buf[1024];
    __shared__ int carry_sh;
    int tid = threadIdx.x;
    if (tid == 0) { carry_sh = 0; g_rowptr[0] = 0; }
    __syncthreads();
    for (int base = 0; base < N_NODES; base += 1024) {
        int v = (base + tid < N_NODES) ? g_deg[base + tid] : 0;
        buf[tid] = v;
        __syncthreads();
        #pragma unroll
        for (int off = 1; off < 1024; off <<= 1) {
            int t = (tid >= off) ? buf[tid - off] : 0;
            __syncthreads();
            buf[tid] += t;
            __syncthreads();
        }
        int incl = buf[tid] + carry_sh;
        if (base + tid < N_NODES) {
            g_rowptr[base + tid + 1] = incl;
            g_fill[base + tid] = incl - v;
        }
        __syncthreads();
        if (tid == 1023) carry_sh = incl;
        __syncthreads();
    }
}
__global__ void csr_scatter_kernel(const int* __restrict__ ei) {
    int e = blockIdx.x * blockDim.x + threadIdx.x;
    if (e >= E_TOT) return;
    int src, dst;
    if (e < N_EDGES) { src = ei[e]; dst = ei[N_EDGES + e]; }
    else             { src = dst = e - N_EDGES; }
    int pos = atomicAdd(&g_fill[dst], 1);
    g_colidx[pos] = src;
}

// ---------------- tensor-core GEMM + fused alphas ----------------
#define LDP 24
__global__ __launch_bounds__(256)
void gat_gemm_kernel(const float* __restrict__ a_s, const float* __restrict__ a_d,
                     int K) {
    __shared__ __nv_bfloat16 As_hi[TILE_M * LDP];
    __shared__ __nv_bfloat16 As_lo[TILE_M * LDP];
    __shared__ __nv_bfloat16 Bs_hi[HH * LDP];
    __shared__ __nv_bfloat16 Bs_lo[HH * LDP];
    __shared__ float as_sh[HH], ad_sh[HH];

    const int tid = threadIdx.x;
    const int wid = tid >> 5;
    const int mw  = wid & 1;
    const int nw  = wid >> 1;
    const int rowBase = blockIdx.x * TILE_M;

    for (int i = tid; i < HH; i += 256) { as_sh[i] = a_s[i]; ad_sh[i] = a_d[i]; }

    wmma::fragment<wmma::accumulator, 16, 16, 16, float> acc[2][4];
    #pragma unroll
    for (int i = 0; i < 2; i++)
        #pragma unroll
        for (int j = 0; j < 4; j++)
            wmma::fill_fragment(acc[i][j], 0.f);

    for (int k0 = 0; k0 < K; k0 += 16) {
        if (tid < 128) {
            int r = tid >> 1, half = tid & 1;
            size_t gsrc = (size_t)(rowBase + r) * K + k0 + half * 8;
            uint4 vh = *(const uint4*)(g_xb_hi + gsrc);
            uint4 vl = *(const uint4*)(g_xb_lo + gsrc);
            *(uint4*)(As_hi + r * LDP + half * 8) = vh;
            *(uint4*)(As_lo + r * LDP + half * 8) = vl;
        }
        #pragma unroll
        for (int t = 0; t < 2; t++) {
            int i = tid + t * 256;
            int n = i >> 1, half = i & 1;
            int gsrc = n * HH + k0 + half * 8;
            uint4 vh = *(const uint4*)(g_wb_hi + gsrc);
            uint4 vl = *(const uint4*)(g_wb_lo + gsrc);
            *(uint4*)(Bs_hi + n * LDP + half * 8) = vh;
            *(uint4*)(Bs_lo + n * LDP + half * 8) = vl;
        }
        __syncthreads();

        wmma::fragment<wmma::matrix_a, 16, 16, 16, __nv_bfloat16, wmma::row_major> a_hi[2], a_lo[2];
        #pragma unroll
        for (int i = 0; i < 2; i++) {
            wmma::load_matrix_sync(a_hi[i], As_hi + (mw * 32 + i * 16) * LDP, LDP);
            wmma::load_matrix_sync(a_lo[i], As_lo + (mw * 32 + i * 16) * LDP, LDP);
        }
        #pragma unroll
        for (int j = 0; j < 4; j++) {
            wmma::fragment<wmma::matrix_b, 16, 16, 16, __nv_bfloat16, wmma::col_major> b_hi, b_lo;
            wmma::load_matrix_sync(b_hi, Bs_hi + (nw * 64 + j * 16) * LDP, LDP);
            wmma::load_matrix_sync(b_lo, Bs_lo + (nw * 64 + j * 16) * LDP, LDP);
            #pragma unroll
            for (int i = 0; i < 2; i++) {
                wmma::mma_sync(acc[i][j], a_hi[i], b_hi, acc[i][j]);
                wmma::mma_sync(acc[i][j], a_hi[i], b_lo, acc[i][j]);
                wmma::mma_sync(acc[i][j], a_lo[i], b_hi, acc[i][j]);
            }
        }
        __syncthreads();
    }

    #pragma unroll
    for (int i = 0; i < 2; i++)
        #pragma unroll
        for (int j = 0; j < 4; j++) {
            float* cp = g_h + (size_t)(rowBase + mw * 32 + i * 16) * HH + nw * 64 + j * 16;
            wmma::store_matrix_sync(cp, acc[i][j], HH, wmma::mem_row_major);
        }
    __syncthreads();

    int r = rowBase + (tid >> 2);
    int hd = tid & 3;
    if (r < N_NODES) {
        const float* hp = g_h + (size_t)r * HH + hd * HID;
        const float* sp = as_sh + hd * HID;
        const float* dp = ad_sh + hd * HID;
        float vs = 0.f, vd = 0.f;
        #pragma unroll
        for (int c = 0; c < HID; c += 4) {
            float4 v = *(const float4*)(hp + c);
            vs += v.x * sp[c] + v.y * sp[c+1] + v.z * sp[c+2] + v.w * sp[c+3];
            vd += v.x * dp[c] + v.y * dp[c+1] + v.z * dp[c+2] + v.w * dp[c+3];
        }
        g_as[r * HEADS + hd] = vs;
        g_ad[r * HEADS + hd] = vd;
    }
}

// ---------------- warp-per-node flash softmax + aggregation + epilogue ----------------
// 8 warps/block, one node per warp. Chunk-of-32 edges; lane j owns edge c0+j for the
// softmax phase; in the feature phase each lane owns 8 contiguous features (one head).
#define WPB 8
__global__ __launch_bounds__(256)
void agg_kernel(const float* __restrict__ bias, int last) {
    const int wrp  = threadIdx.x >> 5;
    const int lane = threadIdx.x & 31;
    const int node = blockIdx.x * WPB + wrp;
    if (node >= N_NODES) return;

    __shared__ float s_al[WPB][32 * 4];
    __shared__ int   s_src[WPB][32];

    const int start = g_rowptr[node];
    const int end   = g_rowptr[node + 1];

    const float4 ad4 = *(const float4*)(g_ad + node * HEADS);

    const int head = lane >> 3;       // feature-phase head of this lane
    float m0 = -INFINITY, m1 = -INFINITY, m2 = -INFINITY, m3 = -INFINITY;
    float s0 = 0.f, s1 = 0.f, s2 = 0.f, s3 = 0.f;
    float acc[8] = {0.f, 0.f, 0.f, 0.f, 0.f, 0.f, 0.f, 0.f};

    for (int c0 = start; c0 < end; c0 += 32) {
        const int len = min(32, end - c0);

        // --- softmax phase: lane = edge ---
        float e0 = -INFINITY, e1 = -INFINITY, e2 = -INFINITY, e3 = -INFINITY;
        if (lane < len) {
            int s = g_colidx[c0 + lane];
            s_src[wrp][lane] = s;
            float4 as4 = *(const float4*)(g_as + s * HEADS);
            e0 = as4.x + ad4.x; e0 = (e0 > 0.f) ? e0 : NEG_SLOPE * e0;
            e1 = as4.y + ad4.y; e1 = (e1 > 0.f) ? e1 : NEG_SLOPE * e1;
            e2 = as4.z + ad4.z; e2 = (e2 > 0.f) ? e2 : NEG_SLOPE * e2;
            e3 = as4.w + ad4.w; e3 = (e3 > 0.f) ? e3 : NEG_SLOPE * e3;
        }
        float n0 = fmaxf(m0, warp_max(e0));
        float n1 = fmaxf(m1, warp_max(e1));
        float n2 = fmaxf(m2, warp_max(e2));
        float n3 = fmaxf(m3, warp_max(e3));
        float sc0 = expf(m0 - n0), sc1 = expf(m1 - n1);
        float sc2 = expf(m2 - n2), sc3 = expf(m3 - n3);
        m0 = n0; m1 = n1; m2 = n2; m3 = n3;

        float q0 = (lane < len) ? expf(e0 - m0) : 0.f;
        float q1 = (lane < len) ? expf(e1 - m1) : 0.f;
        float q2 = (lane < len) ? expf(e2 - m2) : 0.f;
        float q3 = (lane < len) ? expf(e3 - m3) : 0.f;
        s_al[wrp][lane * 4 + 0] = q0;
        s_al[wrp][lane * 4 + 1] = q1;
        s_al[wrp][lane * 4 + 2] = q2;
        s_al[wrp][lane * 4 + 3] = q3;
        s0 = s0 * sc0 + warp_sum(q0);
        s1 = s1 * sc1 + warp_sum(q1);
        s2 = s2 * sc2 + warp_sum(q2);
        s3 = s3 * sc3 + warp_sum(q3);

        // rescale running feature accumulators (one head per lane)
        float accsc = (head == 0) ? sc0 : (head == 1) ? sc1 : (head == 2) ? sc2 : sc3;
        #pragma unroll
        for (int k = 0; k < 8; k++) acc[k] *= accsc;
        __syncwarp();

        // --- feature phase: lane owns features [lane*8, lane*8+8) ---
        #pragma unroll 2
        for (int j = 0; j < len; j++) {
            float a = s_al[wrp][j * 4 + head];
            const float* hp = g_h + (size_t)s_src[wrp][j] * HH + lane * 8;
            float4 v0 = *(const float4*)(hp);
            float4 v1 = *(const float4*)(hp + 4);
            acc[0] += a * v0.x; acc[1] += a * v0.y;
            acc[2] += a * v0.z; acc[3] += a * v0.w;
            acc[4] += a * v1.x; acc[5] += a * v1.y;
            acc[6] += a * v1.z; acc[7] += a * v1.w;
        }
        __syncwarp();
    }

    // --- epilogue: normalize, bias, ELU, store ---
    float rs = 1.f / ((head == 0) ? s0 : (head == 1) ? s1 : (head == 2) ? s2 : s3);
    const int f0 = lane * 8;
    float o[8];
    #pragma unroll
    for (int k = 0; k < 8; k++) {
        float v = acc[k] * rs + bias[f0 + k];
        o[k] = (v > 0.f) ? v : expm1f(v);
    }
    size_t oi = (size_t)node * HH + f0;
    if (last) {
        *(float4*)(g_x + oi)     = make_float4(o[0], o[1], o[2], o[3]);
        *(float4*)(g_x + oi + 4) = make_float4(o[4], o[5], o[6], o[7]);
    } else {
        uint4 vh, vl;
        __nv_bfloat16 h0, l0, h1, l1;
        split2(o[0], h0, l0); split2(o[1], h1, l1);
        vh.x = ((uint32_t)*(uint16_t*)&h1 << 16) | *(uint16_t*)&h0;
        vl.x = ((uint32_t)*(uint16_t*)&l1 << 16) | *(uint16_t*)&l0;
        split2(o[2], h0, l0); split2(o[3], h1, l1);
        vh.y = ((uint32_t)*(uint16_t*)&h1 << 16) | *(uint16_t*)&h0;
        vl.y = ((uint32_t)*(uint16_t*)&l1 << 16) | *(uint16_t*)&l0;
        split2(o[4], h0, l0); split2(o[5], h1, l1);
        vh.z = ((uint32_t)*(uint16_t*)&h1 << 16) | *(uint16_t*)&h0;
        vl.z = ((uint32_t)*(uint16_t*)&l1 << 16) | *(uint16_t*)&l0;
        split2(o[6], h0, l0); split2(o[7], h1, l1);
        vh.w = ((uint32_t)*(uint16_t*)&h1 << 16) | *(uint16_t*)&h0;
        vl.w = ((uint32_t)*(uint16_t*)&l1 << 16) | *(uint16_t*)&l0;
        *(uint4*)(g_xb_hi + oi) = vh;
        *(uint4*)(g_xb_lo + oi) = vl;
    }
}

// ---------------- pooling (batch sorted -> contiguous ranges) ----------------
__global__ void graph_bounds_kernel(const int* __restrict__ batch) {
    int n = blockIdx.x * blockDim.x + threadIdx.x;
    if (n >= N_NODES) return;
    int b = batch[n];
    if (n == 0) {
        for (int g = 0; g <= b; g++) g_gstart[g] = 0;
    } else {
        int bp = batch[n - 1];
        for (int g = bp + 1; g <= b; g++) g_gstart[g] = n;
    }
    if (n == N_NODES - 1) {
        for (int g = b + 1; g <= N_GRAPHS; g++) g_gstart[g] = N_NODES;
    }
}
__global__ void pool_mean_kernel() {
    int g = blockIdx.x, f = threadIdx.x;
    int s = g_gstart[g], e = g_gstart[g + 1];
    float acc = 0.f;
    for (int n = s; n < e; n++)
        acc += g_x[(size_t)n * HH + f];
    g_pool[g * HH + f] = acc / (float)max(e - s, 1);
}

// ---------------- final ----------------
__global__ void final_kernel(const float* __restrict__ Wf, const float* __restrict__ bf,
                             float* __restrict__ out) {
    __shared__ float gs[HH];
    __shared__ float red[OUTF];
    int g = blockIdx.x;
    int t = threadIdx.x;
    for (int i = t; i < HH; i += OUTF) gs[i] = g_pool[g * HH + i];
    __syncthreads();
    float acc = bf[t];
    #pragma unroll 8
    for (int k = 0; k < HH; k++)
        acc += gs[k] * Wf[(size_t)k * OUTF + t];
    red[t] = acc * acc;
    __syncthreads();
    #pragma unroll
    for (int off = 64; off > 0; off >>= 1) {
        if (t < off) red[t] += red[t + off];
        __syncthreads();
    }
    float norm = fmaxf(sqrtf(red[0]), 1e-12f);
    out[(size_t)g * OUTF + t] = acc / norm;
}

// ---------------- host orchestration ----------------
extern "C" void kernel_launch(void* const* d_in, const int* in_sizes, int n_in,
                              void* d_out, int out_size) {
    const float* x     = (const float*)d_in[0];
    const int*   ei    = (const int*)d_in[1];
    const int*   batch = (const int*)d_in[2];
    const float* W[3]  = {(const float*)d_in[3],  (const float*)d_in[7],  (const float*)d_in[11]};
    const float* AS[3] = {(const float*)d_in[4],  (const float*)d_in[8],  (const float*)d_in[12]};
    const float* AD[3] = {(const float*)d_in[5],  (const float*)d_in[9],  (const float*)d_in[13]};
    const float* Bb[3] = {(const float*)d_in[6],  (const float*)d_in[10], (const float*)d_in[14]};
    const float* Wf = (const float*)d_in[15];
    const float* bf = (const float*)d_in[16];
    float* out = (float*)d_out;

    const int threads = 256;
    const int edge_blocks = (E_TOT + threads - 1) / threads;
    const int gemm_blocks = (N_NODES + TILE_M - 1) / TILE_M;
    const int agg_blocks  = (N_NODES + WPB - 1) / WPB;

    csr_zero_kernel<<<(N_NODES + threads - 1) / threads, threads>>>();
    csr_hist_kernel<<<edge_blocks, threads>>>(ei);
    csr_scan_kernel<<<1, 1024>>>();
    csr_scatter_kernel<<<edge_blocks, threads>>>(ei);
    graph_bounds_kernel<<<(N_NODES + threads - 1) / threads, threads>>>(batch);

    prep_x0_kernel<<<(N_PAD * FEAT + threads - 1) / threads, threads>>>(x);

    int Din = FEAT;
    for (int l = 0; l < 3; l++) {
        prep_w_kernel<<<(Din * HH + threads - 1) / threads, threads>>>(W[l], Din);
        gat_gemm_kernel<<<gemm_blocks, 256>>>(AS[l], AD[l], Din);
        agg_kernel<<<agg_blocks, 256>>>(Bb[l], l == 2 ? 1 : 0);
        Din = HH;
    }

    pool_mean_kernel<<<N_GRAPHS, 256>>>();
    final_kernel<<<N_GRAPHS, OUTF>>>(Wf, bf, out);
}

// round 8
// speedup vs baseline: 3.1259x; 1.1452x over previous
#include <cuda_runtime.h>
#include <cuda_bf16.h>
#include <mma.h>
#include <math.h>
#include <cstdint>

using namespace nvcuda;

#define N_NODES  50000
#define TILE_M   128
#define GEMM_BLOCKS ((N_NODES + TILE_M - 1) / TILE_M)     // 392
#define N_PAD    (GEMM_BLOCKS * TILE_M)                   // 50176
#define N_EDGES  800000
#define E_TOT    (N_EDGES + N_NODES)
#define N_GRAPHS 256
#define FEAT     128
#define HID      64
#define HEADS    4
#define HH       (HID*HEADS)           // 256
#define OUTF     128
#define NEG_SLOPE 0.2f

// ---------------- scratch ----------------
__device__ float g_h[(size_t)N_PAD*HH];
__device__ float g_x[(size_t)N_NODES*HH];
__device__ __nv_bfloat16 g_xb_hi[(size_t)N_PAD*HH];
__device__ __nv_bfloat16 g_xb_lo[(size_t)N_PAD*HH];
__device__ __nv_bfloat16 g_wb_hi[3*HH*HH];   // per-layer slots
__device__ __nv_bfloat16 g_wb_lo[3*HH*HH];
__device__ float g_as[N_NODES*HEADS];
__device__ float g_ad[N_NODES*HEADS];
__device__ float g_pool[N_GRAPHS*HH];
__device__ int g_gstart[N_GRAPHS+1];
// CSR
__device__ int g_deg[N_NODES];
__device__ int g_rowptr[N_NODES+1];
__device__ int g_fill[N_NODES];
__device__ int g_colidx[E_TOT];

// ---------------- helpers ----------------
__device__ __forceinline__ void split2(float v, __nv_bfloat16& hi, __nv_bfloat16& lo) {
    hi = __float2bfloat16(v);
    lo = __float2bfloat16(v - __bfloat162float(hi));
}
__device__ __forceinline__ float warp_max(float v) {
    #pragma unroll
    for (int off = 16; off > 0; off >>= 1)
        v = fmaxf(v, __shfl_xor_sync(0xffffffffu, v, off));
    return v;
}
__device__ __forceinline__ float warp_sum(float v) {
    #pragma unroll
    for (int off = 16; off > 0; off >>= 1)
        v += __shfl_xor_sync(0xffffffffu, v, off);
    return v;
}

// ---------------- prep ----------------
__global__ void prep_w_kernel(const float* __restrict__ W, int layer, int K) {
    int idx = blockIdx.x * blockDim.x + threadIdx.x;
    if (idx >= K * HH) return;
    int k = idx >> 8, n = idx & (HH - 1);
    __nv_bfloat16 hi, lo;
    split2(W[idx], hi, lo);
    g_wb_hi[layer * HH * HH + n * HH + k] = hi;
    g_wb_lo[layer * HH * HH + n * HH + k] = lo;
}
__global__ void prep_x0_kernel(const float* __restrict__ x) {
    int idx = blockIdx.x * blockDim.x + threadIdx.x;
    if (idx >= N_PAD * FEAT) return;
    float v = (idx < N_NODES * FEAT) ? x[idx] : 0.f;
    __nv_bfloat16 hi, lo;
    split2(v, hi, lo);
    g_xb_hi[idx] = hi;
    g_xb_lo[idx] = lo;
}

// ---------------- CSR build ----------------
__global__ void csr_zero_kernel() {
    int i = blockIdx.x * blockDim.x + threadIdx.x;
    if (i < N_NODES) g_deg[i] = 0;
}
__global__ void csr_hist_kernel(const int* __restrict__ ei) {
    int e = blockIdx.x * blockDim.x + threadIdx.x;
    if (e >= E_TOT) return;
    int dst = (e < N_EDGES) ? ei[N_EDGES + e] : e - N_EDGES;
    atomicAdd(&g_deg[dst], 1);
}
__global__ void csr_scan_kernel() {   // 1 block, 1024 threads, warp-shuffle scan
    __shared__ int warp_sums[32];
    __shared__ int carry_sh;
    const int tid  = threadIdx.x;
    const int lane = tid & 31;
    const int wid  = tid >> 5;
    if (tid == 0) { carry_sh = 0; g_rowptr[0] = 0; }
    __syncthreads();
    for (int base = 0; base < N_NODES; base += 1024) {
        int v = (base + tid < N_NODES) ? g_deg[base + tid] : 0;
        int x = v;
        #pragma unroll
        for (int off = 1; off < 32; off <<= 1) {
            int y = __shfl_up_sync(0xffffffffu, x, off);
            if (lane >= off) x += y;
        }
        if (lane == 31) warp_sums[wid] = x;
        __syncthreads();
        if (wid == 0) {
            int w = warp_sums[lane];
            #pragma unroll
            for (int off = 1; off < 32; off <<= 1) {
                int y = __shfl_up_sync(0xffffffffu, w, off);
                if (lane >= off) w += y;
            }
            warp_sums[lane] = w;
        }
        __syncthreads();
        int incl = x + (wid > 0 ? warp_sums[wid - 1] : 0) + carry_sh;
        if (base + tid < N_NODES) {
            g_rowptr[base + tid + 1] = incl;
            g_fill[base + tid] = incl - v;
        }
        __syncthreads();
        if (tid == 1023) carry_sh = incl;
        __syncthreads();
    }
}
__global__ void csr_scatter_kernel(const int* __restrict__ ei) {
    int e = blockIdx.x * blockDim.x + threadIdx.x;
    if (e >= E_TOT) return;
    int src, dst;
    if (e < N_EDGES) { src = ei[e]; dst = ei[N_EDGES + e]; }
    else             { src = dst = e - N_EDGES; }
    int pos = atomicAdd(&g_fill[dst], 1);
    g_colidx[pos] = src;
}

// ---------------- tensor-core GEMM (128x256), register-prefetch pipeline, fused alphas ----------------
#define LDP 24
__global__ __launch_bounds__(512)
void gat_gemm_kernel(int layer, const float* __restrict__ a_s, const float* __restrict__ a_d,
                     int K) {
    __shared__ __nv_bfloat16 As_hi[TILE_M * LDP];
    __shared__ __nv_bfloat16 As_lo[TILE_M * LDP];
    __shared__ __nv_bfloat16 Bs_hi[HH * LDP];
    __shared__ __nv_bfloat16 Bs_lo[HH * LDP];
    __shared__ float as_sh[HH], ad_sh[HH];

    const int tid = threadIdx.x;
    const int wid = tid >> 5;          // 0..15
    const int mw  = wid & 3;           // row group (32 rows each)
    const int nw  = wid >> 2;          // col group (64 cols each)
    const int rowBase = blockIdx.x * TILE_M;

    const __nv_bfloat16* __restrict__ whi = g_wb_hi + (size_t)layer * HH * HH;
    const __nv_bfloat16* __restrict__ wlo = g_wb_lo + (size_t)layer * HH * HH;

    if (tid < HH) { as_sh[tid] = a_s[tid]; ad_sh[tid] = a_d[tid]; }

    // staging roles
    const int  ar   = (tid & 255) >> 1;         // A row 0..127
    const int  ah   = tid & 1;                  // A half (8 bf16)
    const bool aIsLo = (tid >= 256);
    const __nv_bfloat16* Asrc = aIsLo ? g_xb_lo : g_xb_hi;
    __nv_bfloat16* Asm = aIsLo ? As_lo : As_hi;
    const int  bn   = tid >> 1;                 // B row 0..255
    const int  bh   = tid & 1;

    wmma::fragment<wmma::accumulator, 16, 16, 16, float> acc[2][4];
    #pragma unroll
    for (int i = 0; i < 2; i++)
        #pragma unroll
        for (int j = 0; j < 4; j++)
            wmma::fill_fragment(acc[i][j], 0.f);

    const int nsteps = K >> 4;
    // prefetch chunk 0
    uint4 pa  = *(const uint4*)(Asrc + (size_t)(rowBase + ar) * K + ah * 8);
    uint4 pbh = *(const uint4*)(whi + bn * HH + bh * 8);
    uint4 pbl = *(const uint4*)(wlo + bn * HH + bh * 8);

    for (int c = 0; c < nsteps; c++) {
        *(uint4*)(Asm + ar * LDP + ah * 8)   = pa;
        *(uint4*)(Bs_hi + bn * LDP + bh * 8) = pbh;
        *(uint4*)(Bs_lo + bn * LDP + bh * 8) = pbl;
        __syncthreads();
        if (c + 1 < nsteps) {
            int k0 = (c + 1) << 4;
            pa  = *(const uint4*)(Asrc + (size_t)(rowBase + ar) * K + k0 + ah * 8);
            pbh = *(const uint4*)(whi + bn * HH + k0 + bh * 8);
            pbl = *(const uint4*)(wlo + bn * HH + k0 + bh * 8);
        }
        wmma::fragment<wmma::matrix_a, 16, 16, 16, __nv_bfloat16, wmma::row_major> a_hi[2], a_lo[2];
        #pragma unroll
        for (int i = 0; i < 2; i++) {
            wmma::load_matrix_sync(a_hi[i], As_hi + (mw * 32 + i * 16) * LDP, LDP);
            wmma::load_matrix_sync(a_lo[i], As_lo + (mw * 32 + i * 16) * LDP, LDP);
        }
        #pragma unroll
        for (int j = 0; j < 4; j++) {
            wmma::fragment<wmma::matrix_b, 16, 16, 16, __nv_bfloat16, wmma::col_major> b_hi, b_lo;
            wmma::load_matrix_sync(b_hi, Bs_hi + (nw * 64 + j * 16) * LDP, LDP);
            wmma::load_matrix_sync(b_lo, Bs_lo + (nw * 64 + j * 16) * LDP, LDP);
            #pragma unroll
            for (int i = 0; i < 2; i++) {
                wmma::mma_sync(acc[i][j], a_hi[i], b_hi, acc[i][j]);
                wmma::mma_sync(acc[i][j], a_hi[i], b_lo, acc[i][j]);
                wmma::mma_sync(acc[i][j], a_lo[i], b_hi, acc[i][j]);
            }
        }
        __syncthreads();
    }

    #pragma unroll
    for (int i = 0; i < 2; i++)
        #pragma unroll
        for (int j = 0; j < 4; j++) {
            float* cp = g_h + (size_t)(rowBase + mw * 32 + i * 16) * HH + nw * 64 + j * 16;
            wmma::store_matrix_sync(cp, acc[i][j], HH, wmma::mem_row_major);
        }
    __syncthreads();

    // fused alphas: thread -> (row = tid>>2, head = tid&3)
    int r = rowBase + (tid >> 2);
    int hd = tid & 3;
    if (r < N_NODES) {
        const float* hp = g_h + (size_t)r * HH + hd * HID;
        const float* sp = as_sh + hd * HID;
        const float* dp = ad_sh + hd * HID;
        float vs = 0.f, vd = 0.f;
        #pragma unroll
        for (int c = 0; c < HID; c += 4) {
            float4 v = *(const float4*)(hp + c);
            vs += v.x * sp[c] + v.y * sp[c+1] + v.z * sp[c+2] + v.w * sp[c+3];
            vd += v.x * dp[c] + v.y * dp[c+1] + v.z * dp[c+2] + v.w * dp[c+3];
        }
        g_as[r * HEADS + hd] = vs;
        g_ad[r * HEADS + hd] = vd;
    }
}

// ---------------- warp-per-node flash softmax + aggregation + epilogue ----------------
#define WPB 8
__global__ __launch_bounds__(256)
void agg_kernel(const float* __restrict__ bias, int last) {
    const int wrp  = threadIdx.x >> 5;
    const int lane = threadIdx.x & 31;
    const int node = blockIdx.x * WPB + wrp;
    if (node >= N_NODES) return;

    __shared__ float s_al[WPB][32 * 4];
    __shared__ int   s_src[WPB][32];

    const int start = g_rowptr[node];
    const int end   = g_rowptr[node + 1];

    const float4 ad4 = *(const float4*)(g_ad + node * HEADS);

    const int head = lane >> 3;
    float m0 = -INFINITY, m1 = -INFINITY, m2 = -INFINITY, m3 = -INFINITY;
    float s0 = 0.f, s1 = 0.f, s2 = 0.f, s3 = 0.f;
    float acc[8] = {0.f, 0.f, 0.f, 0.f, 0.f, 0.f, 0.f, 0.f};

    for (int c0 = start; c0 < end; c0 += 32) {
        const int len = min(32, end - c0);

        float e0 = -INFINITY, e1 = -INFINITY, e2 = -INFINITY, e3 = -INFINITY;
        if (lane < len) {
            int s = g_colidx[c0 + lane];
            s_src[wrp][lane] = s;
            float4 as4 = *(const float4*)(g_as + s * HEADS);
            e0 = as4.x + ad4.x; e0 = (e0 > 0.f) ? e0 : NEG_SLOPE * e0;
            e1 = as4.y + ad4.y; e1 = (e1 > 0.f) ? e1 : NEG_SLOPE * e1;
            e2 = as4.z + ad4.z; e2 = (e2 > 0.f) ? e2 : NEG_SLOPE * e2;
            e3 = as4.w + ad4.w; e3 = (e3 > 0.f) ? e3 : NEG_SLOPE * e3;
        }
        float n0 = fmaxf(m0, warp_max(e0));
        float n1 = fmaxf(m1, warp_max(e1));
        float n2 = fmaxf(m2, warp_max(e2));
        float n3 = fmaxf(m3, warp_max(e3));
        float sc0 = expf(m0 - n0), sc1 = expf(m1 - n1);
        float sc2 = expf(m2 - n2), sc3 = expf(m3 - n3);
        m0 = n0; m1 = n1; m2 = n2; m3 = n3;

        float q0 = (lane < len) ? expf(e0 - m0) : 0.f;
        float q1 = (lane < len) ? expf(e1 - m1) : 0.f;
        float q2 = (lane < len) ? expf(e2 - m2) : 0.f;
        float q3 = (lane < len) ? expf(e3 - m3) : 0.f;
        s_al[wrp][lane * 4 + 0] = q0;
        s_al[wrp][lane * 4 + 1] = q1;
        s_al[wrp][lane * 4 + 2] = q2;
        s_al[wrp][lane * 4 + 3] = q3;
        s0 = s0 * sc0 + warp_sum(q0);
        s1 = s1 * sc1 + warp_sum(q1);
        s2 = s2 * sc2 + warp_sum(q2);
        s3 = s3 * sc3 + warp_sum(q3);

        float accsc = (head == 0) ? sc0 : (head == 1) ? sc1 : (head == 2) ? sc2 : sc3;
        #pragma unroll
        for (int k = 0; k < 8; k++) acc[k] *= accsc;
        __syncwarp();

        #pragma unroll 2
        for (int j = 0; j < len; j++) {
            float a = s_al[wrp][j * 4 + head];
            const float* hp = g_h + (size_t)s_src[wrp][j] * HH + lane * 8;
            float4 v0 = *(const float4*)(hp);
            float4 v1 = *(const float4*)(hp + 4);
            acc[0] += a * v0.x; acc[1] += a * v0.y;
            acc[2] += a * v0.z; acc[3] += a * v0.w;
            acc[4] += a * v1.x; acc[5] += a * v1.y;
            acc[6] += a * v1.z; acc[7] += a * v1.w;
        }
        __syncwarp();
    }

    float rs = 1.f / ((head == 0) ? s0 : (head == 1) ? s1 : (head == 2) ? s2 : s3);
    const int f0 = lane * 8;
    float o[8];
    #pragma unroll
    for (int k = 0; k < 8; k++) {
        float v = acc[k] * rs + bias[f0 + k];
        o[k] = (v > 0.f) ? v : expm1f(v);
    }
    size_t oi = (size_t)node * HH + f0;
    if (last) {
        *(float4*)(g_x + oi)     = make_float4(o[0], o[1], o[2], o[3]);
        *(float4*)(g_x + oi + 4) = make_float4(o[4], o[5], o[6], o[7]);
    } else {
        uint4 vh, vl;
        __nv_bfloat16 h0, l0, h1, l1;
        split2(o[0], h0, l0); split2(o[1], h1, l1);
        vh.x = ((uint32_t)*(uint16_t*)&h1 << 16) | *(uint16_t*)&h0;
        vl.x = ((uint32_t)*(uint16_t*)&l1 << 16) | *(uint16_t*)&l0;
        split2(o[2], h0, l0); split2(o[3], h1, l1);
        vh.y = ((uint32_t)*(uint16_t*)&h1 << 16) | *(uint16_t*)&h0;
        vl.y = ((uint32_t)*(uint16_t*)&l1 << 16) | *(uint16_t*)&l0;
        split2(o[4], h0, l0); split2(o[5], h1, l1);
        vh.z = ((uint32_t)*(uint16_t*)&h1 << 16) | *(uint16_t*)&h0;
        vl.z = ((uint32_t)*(uint16_t*)&l1 << 16) | *(uint16_t*)&l0;
        split2(o[6], h0, l0); split2(o[7], h1, l1);
        vh.w = ((uint32_t)*(uint16_t*)&h1 << 16) | *(uint16_t*)&h0;
        vl.w = ((uint32_t)*(uint16_t*)&l1 << 16) | *(uint16_t*)&l0;
        *(uint4*)(g_xb_hi + oi) = vh;
        *(uint4*)(g_xb_lo + oi) = vl;
    }
}

// ---------------- pooling ----------------
__global__ void graph_bounds_kernel(const int* __restrict__ batch) {
    int n = blockIdx.x * blockDim.x + threadIdx.x;
    if (n >= N_NODES) return;
    int b = batch[n];
    if (n == 0) {
        for (int g = 0; g <= b; g++) g_gstart[g] = 0;
    } else {
        int bp = batch[n - 1];
        for (int g = bp + 1; g <= b; g++) g_gstart[g] = n;
    }
    if (n == N_NODES - 1) {
        for (int g = b + 1; g <= N_GRAPHS; g++) g_gstart[g] = N_NODES;
    }
}
__global__ void pool_mean_kernel() {
    int g = blockIdx.x, f = threadIdx.x;
    int s = g_gstart[g], e = g_gstart[g + 1];
    float acc = 0.f;
    for (int n = s; n < e; n++)
        acc += g_x[(size_t)n * HH + f];
    g_pool[g * HH + f] = acc / (float)max(e - s, 1);
}

// ---------------- final ----------------
__global__ void final_kernel(const float* __restrict__ Wf, const float* __restrict__ bf,
                             float* __restrict__ out) {
    __shared__ float gs[HH];
    __shared__ float red[OUTF];
    int g = blockIdx.x;
    int t = threadIdx.x;
    for (int i = t; i < HH; i += OUTF) gs[i] = g_pool[g * HH + i];
    __syncthreads();
    float acc = bf[t];
    #pragma unroll 8
    for (int k = 0; k < HH; k++)
        acc += gs[k] * Wf[(size_t)k * OUTF + t];
    red[t] = acc * acc;
    __syncthreads();
    #pragma unroll
    for (int off = 64; off > 0; off >>= 1) {
        if (t < off) red[t] += red[t + off];
        __syncthreads();
    }
    float norm = fmaxf(sqrtf(red[0]), 1e-12f);
    out[(size_t)g * OUTF + t] = acc / norm;
}

// ---------------- host orchestration ----------------
extern "C" void kernel_launch(void* const* d_in, const int* in_sizes, int n_in,
                              void* d_out, int out_size) {
    const float* x     = (const float*)d_in[0];
    const int*   ei    = (const int*)d_in[1];
    const int*   batch = (const int*)d_in[2];
    const float* W[3]  = {(const float*)d_in[3],  (const float*)d_in[7],  (const float*)d_in[11]};
    const float* AS[3] = {(const float*)d_in[4],  (const float*)d_in[8],  (const float*)d_in[12]};
    const float* AD[3] = {(const float*)d_in[5],  (const float*)d_in[9],  (const float*)d_in[13]};
    const float* Bb[3] = {(const float*)d_in[6],  (const float*)d_in[10], (const float*)d_in[14]};
    const float* Wf = (const float*)d_in[15];
    const float* bf = (const float*)d_in[16];
    float* out = (float*)d_out;

    // persistent side stream + events (resources created once; identical work each call)
    static cudaStream_t s2 = [] {
        cudaStream_t s; cudaStreamCreateWithFlags(&s, cudaStreamNonBlocking); return s;
    }();
    static cudaEvent_t eFork = [] {
        cudaEvent_t e; cudaEventCreateWithFlags(&e, cudaEventDisableTiming); return e;
    }();
    static cudaEvent_t eW0 = [] {
        cudaEvent_t e; cudaEventCreateWithFlags(&e, cudaEventDisableTiming); return e;
    }();
    static cudaEvent_t eCSR = [] {
        cudaEvent_t e; cudaEventCreateWithFlags(&e, cudaEventDisableTiming); return e;
    }();

    const int threads = 256;
    const int edge_blocks = (E_TOT + threads - 1) / threads;
    const int agg_blocks  = (N_NODES + WPB - 1) / WPB;

    // fork side stream off the main (capture) stream
    cudaEventRecord(eFork, 0);
    cudaStreamWaitEvent(s2, eFork, 0);

    // side stream: weight prep + CSR build + graph bounds
    prep_w_kernel<<<(FEAT * HH + threads - 1) / threads, threads, 0, s2>>>(W[0], 0, FEAT);
    cudaEventRecord(eW0, s2);
    prep_w_kernel<<<(HH * HH + threads - 1) / threads, threads, 0, s2>>>(W[1], 1, HH);
    prep_w_kernel<<<(HH * HH + threads - 1) / threads, threads, 0, s2>>>(W[2], 2, HH);
    csr_zero_kernel<<<(N_NODES + threads - 1) / threads, threads, 0, s2>>>();
    csr_hist_kernel<<<edge_blocks, threads, 0, s2>>>(ei);
    csr_scan_kernel<<<1, 1024, 0, s2>>>();
    csr_scatter_kernel<<<edge_blocks, threads, 0, s2>>>(ei);
    graph_bounds_kernel<<<(N_NODES + threads - 1) / threads, threads, 0, s2>>>(batch);
    cudaEventRecord(eCSR, s2);

    // main stream: input prep + layer 1 GEMM overlap with CSR build
    prep_x0_kernel<<<(N_PAD * FEAT + threads - 1) / threads, threads>>>(x);
    cudaStreamWaitEvent(0, eW0, 0);
    gat_gemm_kernel<<<GEMM_BLOCKS, 512>>>(0, AS[0], AD[0], FEAT);
    cudaStreamWaitEvent(0, eCSR, 0);
    agg_kernel<<<agg_blocks, 256>>>(Bb[0], 0);

    gat_gemm_kernel<<<GEMM_BLOCKS, 512>>>(1, AS[1], AD[1], HH);
    agg_kernel<<<agg_blocks, 256>>>(Bb[1], 0);

    gat_gemm_kernel<<<GEMM_BLOCKS, 512>>>(2, AS[2], AD[2], HH);
    agg_kernel<<<agg_blocks, 256>>>(Bb[2], 1);

    pool_mean_kernel<<<N_GRAPHS, 256>>>();
    final_kernel<<<N_GRAPHS, OUTF>>>(Wf, bf, out);
}